// round 9
// baseline (speedup 1.0000x reference)
#include <cuda_runtime.h>
#include <cstdint>
#include <cstddef>

#define BR   4096
#define MF   20000
#define EMB  100
#define NPAD 128
#define KC   32
#define EPSB 1e-5f
#define STG  24576          // Ah 4K | Al 4K | Wh 8K | Wl 8K
#define NSTG 3

typedef unsigned long long u64;
typedef unsigned int u32;

// ---------------- device scratch ----------------
__device__ int   g_mode;                       // 0=int32, 1=byte bool, 2=float32
__device__ unsigned short g_Wh[NPAD * MF];     // bf16 hi split, rows 100..127 zero
__device__ unsigned short g_Wl[NPAD * MF];     // bf16 lo split
__device__ float g_Part[2][2][BR][104];        // ksplit, pass, row, col
__device__ float g_H1[2 * BR * EMB];
__device__ float g_H2[2 * BR * EMB];
__device__ float g_H3[2 * BR * EMB];
__device__ float g_P[3][2][128][2][EMB];
__device__ float g_bns[3][2][EMB];
__device__ float g_bnb[3][2][EMB];

// ---------------- helpers ----------------
__device__ __forceinline__ u32 smem_u32(const void* p) {
    u32 a; asm("{ .reg .u64 t; cvta.to.shared.u64 t, %1; cvt.u32.u64 %0, t; }" : "=r"(a) : "l"(p));
    return a;
}
__device__ __forceinline__ void ldsm4(u32& r0, u32& r1, u32& r2, u32& r3, u32 addr) {
    asm volatile("ldmatrix.sync.aligned.m8n8.x4.shared.b16 {%0,%1,%2,%3}, [%4];"
        : "=r"(r0), "=r"(r1), "=r"(r2), "=r"(r3) : "r"(addr));
}
__device__ __forceinline__ void mma16816(float* d, const u32* a, const u32* b) {
    asm volatile("mma.sync.aligned.m16n8k16.row.col.f32.bf16.bf16.f32 "
        "{%0,%1,%2,%3}, {%4,%5,%6,%7}, {%8,%9}, {%0,%1,%2,%3};"
        : "+f"(d[0]), "+f"(d[1]), "+f"(d[2]), "+f"(d[3])
        : "r"(a[0]), "r"(a[1]), "r"(a[2]), "r"(a[3]), "r"(b[0]), "r"(b[1]));
}
__device__ __forceinline__ void cp16(u32 dst, const void* src) {
    asm volatile("cp.async.cg.shared.global [%0], [%1], 16;"
        :: "r"(dst), "l"(src) : "memory");
}
#define CP_COMMIT() asm volatile("cp.async.commit_group;" ::: "memory")
#define CP_WAIT1()  asm volatile("cp.async.wait_group 1;" ::: "memory")
#define CP_WAIT0()  asm volatile("cp.async.wait_group 0;" ::: "memory")

// 64B-row swizzle
__device__ __forceinline__ u32 sw64(u32 row, u32 colb) {
    return row * 64 + (colb ^ (((row >> 1) & 3) << 4));
}
// bf16 split
__device__ __forceinline__ u32 prmt_hi(float a, float b) {
    u32 r; asm("prmt.b32 %0, %1, %2, 0x7632;" : "=r"(r)
               : "r"(__float_as_uint(a)), "r"(__float_as_uint(b)));
    return r;
}
__device__ __forceinline__ u32 pk_lo(float a, float b) {
    float la = a - __uint_as_float(__float_as_uint(a) & 0xffff0000u);
    float lb = b - __uint_as_float(__float_as_uint(b) & 0xffff0000u);
    u32 r; asm("cvt.rn.bf16x2.f32 %0, %1, %2;" : "=r"(r) : "f"(lb), "f"(la));
    return r;
}
// packed f32x2
__device__ __forceinline__ u64 pk2(float lo, float hi) {
    u64 d; asm("mov.b64 %0, {%1, %2};" : "=l"(d) : "f"(lo), "f"(hi)); return d;
}
__device__ __forceinline__ u64 fma2(u64 a, u64 b, u64 c) {
    u64 d; asm("fma.rn.f32x2 %0, %1, %2, %3;" : "=l"(d) : "l"(a), "l"(b), "l"(c)); return d;
}
__device__ __forceinline__ float2 upk2(u64 v) {
    float2 r; asm("mov.b64 {%0, %1}, %2;" : "=f"(r.x), "=f"(r.y) : "l"(v)); return r;
}

// ---------------- mask dtype classifier ----------------
__global__ void k_detect(const unsigned char* __restrict__ m) {
    __shared__ int s_nz, s_gt;
    if (threadIdx.x == 0) { s_nz = 0; s_gt = 0; }
    __syncthreads();
    int nz = 0, gt = 0;
    for (int i = threadIdx.x; i < 65536; i += blockDim.x) {
        unsigned char v = m[i];
        nz += (v != 0); gt += (v > 1);
    }
    atomicAdd(&s_nz, nz); atomicAdd(&s_gt, gt);
    __syncthreads();
    if (threadIdx.x == 0)
        g_mode = (s_gt > 64) ? 2 : (s_nz > 24576) ? 1 : 0;
}

// ---------------- W split precompute ----------------
__global__ void k_wcvt(const float* __restrict__ w, int base) {
    int i = base + blockIdx.x * blockDim.x + threadIdx.x;
    if (i >= NPAD * MF / 2) return;
    int row = i / (MF / 2), within = i % (MF / 2);
    if (row < EMB) {
        float2 v = *(const float2*)(w + (size_t)row * MF + 2 * within);
        ((u32*)g_Wh)[i] = prmt_hi(v.x, v.y);
        ((u32*)g_Wl)[i] = pk_lo(v.x, v.y);
    } else {
        ((u32*)g_Wh)[i] = 0u;
        ((u32*)g_Wl)[i] = 0u;
    }
}

// ---------------- Layer 1: split-bf16 mma.sync, latency-hidden pipeline ----
// grid=256: p = bid&1, ks2 = (bid>>1)&1, tile = bid>>2 (64 rows). 2 CTAs/SM.
// Stage (24KB): Ah@0 | Al@4K | Wh@8K | Wl@16K. 64B rows (KC=32 bf16).
__global__ __launch_bounds__(256, 2)
void k_big(const float* __restrict__ x, const void* __restrict__ mk,
           const float* __restrict__ xr)
{
    extern __shared__ char smem[];
    const u32 sb = smem_u32(smem);
    const int t = threadIdx.x;
    const int w = t >> 5, lane = t & 31;
    const int p = blockIdx.x & 1, ks2 = (blockIdx.x >> 1) & 1, tile = blockIdx.x >> 2;
    const int r0g = tile * 64;
    const int ci0 = ks2 ? 313 : 0;
    const int n   = ks2 ? 312 : 313;
    const int wm = w >> 2, nc = w & 3;
    const int mode = g_mode;

    // A staging: one 16B chunk per thread per split: arow = t>>2, seg = t&3
    const int arow = t >> 2, seg = t & 3;
    const size_t abase = (size_t)(r0g + arow) * MF + (size_t)(ci0 * KC) + seg * 8;
    const u32 aoff = sw64(arow, seg * 16);

    // W cp.async: 2 chunks of 16B per thread per split
    u32 woff0, woff1; size_t wsrc0, wsrc1;
    {
        int g0 = t, g1 = t + 256;
        int r0w = g0 >> 2, s0 = g0 & 3, r1w = g1 >> 2, s1 = g1 & 3;
        woff0 = sw64(r0w, s0 * 16);
        woff1 = sw64(r1w, s1 * 16);
        wsrc0 = (size_t)r0w * MF + (size_t)(ci0 * KC) + s0 * 8;
        wsrc1 = (size_t)r1w * MF + (size_t)(ci0 * KC) + s1 * 8;
    }

    // raw staged loads (live across COMP) + packed A
    float rv[8], rq[8];
    u32 rm[8];
    uint4 HA, LA;

    float acc[2][4][4];
    #pragma unroll
    for (int mf = 0; mf < 2; mf++)
        #pragma unroll
        for (int nf = 0; nf < 4; nf++)
            #pragma unroll
            for (int e = 0; e < 4; e++) acc[mf][nf][e] = 0.f;

    auto CPW = [&](int j) {           // local chunk j -> stage j%3
        const u32 base = sb + (j % 3) * STG;
        const size_t ko = (size_t)j * KC;
        cp16(base +  8192 + woff0, g_Wh + wsrc0 + ko);
        cp16(base +  8192 + woff1, g_Wh + wsrc1 + ko);
        cp16(base + 16384 + woff0, g_Wl + wsrc0 + ko);
        cp16(base + 16384 + woff1, g_Wl + wsrc1 + ko);
    };

    auto LOADRAW = [&](int j) {       // issue LDGs, keep raw in regs
        const size_t g = abase + (size_t)j * KC;
        float4 x0 = *(const float4*)(x + g);
        float4 x1 = *(const float4*)(x + g + 4);
        rv[0]=x0.x; rv[1]=x0.y; rv[2]=x0.z; rv[3]=x0.w;
        rv[4]=x1.x; rv[5]=x1.y; rv[6]=x1.z; rv[7]=x1.w;
        if (p == 1) {
            float4 q0 = *(const float4*)(xr + g);
            float4 q1 = *(const float4*)(xr + g + 4);
            rq[0]=q0.x; rq[1]=q0.y; rq[2]=q0.z; rq[3]=q0.w;
            rq[4]=q1.x; rq[5]=q1.y; rq[6]=q1.z; rq[7]=q1.w;
            if (mode == 1) {
                uint2 mm = *(const uint2*)((const unsigned char*)mk + g);
                rm[0] = mm.x; rm[1] = mm.y;
            } else if (mode == 0) {
                uint4 m0 = *(const uint4*)((const int*)mk + g);
                uint4 m1 = *(const uint4*)((const int*)mk + g + 4);
                rm[0]=m0.x; rm[1]=m0.y; rm[2]=m0.z; rm[3]=m0.w;
                rm[4]=m1.x; rm[5]=m1.y; rm[6]=m1.z; rm[7]=m1.w;
            } else {
                float4 m0 = *(const float4*)((const float*)mk + g);
                float4 m1 = *(const float4*)((const float*)mk + g + 4);
                rm[0]=__float_as_uint(m0.x); rm[1]=__float_as_uint(m0.y);
                rm[2]=__float_as_uint(m0.z); rm[3]=__float_as_uint(m0.w);
                rm[4]=__float_as_uint(m1.x); rm[5]=__float_as_uint(m1.y);
                rm[6]=__float_as_uint(m1.z); rm[7]=__float_as_uint(m1.w);
            }
        }
    };

    auto CVT = [&]() {                // select + pack into HA/LA
        float v[8];
        #pragma unroll
        for (int m = 0; m < 8; m++) v[m] = rv[m];
        if (p == 1) {
            if (mode == 1) {
                #pragma unroll
                for (int m = 0; m < 4; m++) {
                    if ((rm[0] >> (m*8)) & 0xff) v[m]   = rq[m];
                    if ((rm[1] >> (m*8)) & 0xff) v[m+4] = rq[m+4];
                }
            } else if (mode == 0) {
                #pragma unroll
                for (int m = 0; m < 8; m++) if (rm[m]) v[m] = rq[m];
            } else {
                #pragma unroll
                for (int m = 0; m < 8; m++)
                    if ((rm[m] << 1) != 0u) v[m] = rq[m];   // float != 0 (incl -0 -> 0)
            }
        }
        HA.x = prmt_hi(v[0],v[1]); HA.y = prmt_hi(v[2],v[3]);
        HA.z = prmt_hi(v[4],v[5]); HA.w = prmt_hi(v[6],v[7]);
        LA.x = pk_lo (v[0],v[1]); LA.y = pk_lo (v[2],v[3]);
        LA.z = pk_lo (v[4],v[5]); LA.w = pk_lo (v[6],v[7]);
    };

    auto STORE_A = [&](int j) {
        char* bs = smem + (j % 3) * STG;
        *(uint4*)(bs +        aoff) = HA;
        *(uint4*)(bs + 4096 + aoff) = LA;
    };

    // COMP lane addressing
    const u32 rowa = wm * 32 + (lane & 15);
    const u32 c16A = ((lane >> 4) & 1) * 16;
    const u32 xrA  = ((rowa >> 1) & 3) << 4;
    const u32 baseA0 = rowa * 64;
    const u32 baseA1 = (rowa + 16) * 64;
    const u32 xrA1 = (((rowa + 16) >> 1) & 3) << 4;
    const u32 nrow = nc * 32 + ((lane >> 4) & 1) * 8 + (lane & 7);
    const u32 c16B = ((lane >> 3) & 1) * 16;
    const u32 baseB0 = nrow * 64,        xrB0 = ((nrow >> 1) & 3) << 4;
    const u32 baseB1 = (nrow + 16) * 64, xrB1 = (((nrow + 16) >> 1) & 3) << 4;

    auto COMP = [&](int j) {
        const u32 bs = sb + (j % 3) * STG;
        const u32 Ah = bs, Al = bs + 4096, Wh = bs + 8192, Wl = bs + 16384;
        #pragma unroll
        for (int ks = 0; ks < 2; ks++) {
            const u32 kb = ks * 32;
            u32 aH[2][4], aL[2][4], bH[4][2], bL[4][2];
            ldsm4(aH[0][0], aH[0][1], aH[0][2], aH[0][3], Ah + baseA0 + ((kb + c16A) ^ xrA));
            ldsm4(aH[1][0], aH[1][1], aH[1][2], aH[1][3], Ah + baseA1 + ((kb + c16A) ^ xrA1));
            ldsm4(aL[0][0], aL[0][1], aL[0][2], aL[0][3], Al + baseA0 + ((kb + c16A) ^ xrA));
            ldsm4(aL[1][0], aL[1][1], aL[1][2], aL[1][3], Al + baseA1 + ((kb + c16A) ^ xrA1));
            ldsm4(bH[0][0], bH[0][1], bH[1][0], bH[1][1], Wh + baseB0 + ((kb + c16B) ^ xrB0));
            ldsm4(bH[2][0], bH[2][1], bH[3][0], bH[3][1], Wh + baseB1 + ((kb + c16B) ^ xrB1));
            ldsm4(bL[0][0], bL[0][1], bL[1][0], bL[1][1], Wl + baseB0 + ((kb + c16B) ^ xrB0));
            ldsm4(bL[2][0], bL[2][1], bL[3][0], bL[3][1], Wl + baseB1 + ((kb + c16B) ^ xrB1));
            #pragma unroll
            for (int mf = 0; mf < 2; mf++)
                #pragma unroll
                for (int nf = 0; nf < 4; nf++) {
                    mma16816(acc[mf][nf], aH[mf], bH[nf]);
                    mma16816(acc[mf][nf], aH[mf], bL[nf]);
                    mma16816(acc[mf][nf], aL[mf], bH[nf]);
                }
        }
    };

    // prologue: chunk0 packed+stored; chunk1 packed in regs; W0,W1 in flight
    CPW(0); CP_COMMIT();
    CPW(1); CP_COMMIT();
    LOADRAW(0); CVT(); STORE_A(0);
    LOADRAW(1); CVT();               // HA/LA = chunk 1
    CP_WAIT1();                      // W(0) complete
    __syncthreads();

    for (int i = 0; i < n; i++) {
        if (i + 1 < n) STORE_A(i + 1);           // HA/LA from prev iter
        if (i + 2 < n) LOADRAW(i + 2);           // LDGs covered by COMP
        COMP(i);
        if (i + 2 < n) {
            CVT();                               // raw -> HA/LA for next iter
            CPW(i + 2); CP_COMMIT(); CP_WAIT1(); // W(i+1) complete
        } else {
            CP_WAIT0();
        }
        __syncthreads();
    }

    // epilogue: raw partials -> g_Part
    float* Pp = &g_Part[ks2][p][0][0];
    const int gq = lane >> 2, tt = lane & 3;
    #pragma unroll
    for (int mf = 0; mf < 2; mf++)
        #pragma unroll
        for (int nf = 0; nf < 4; nf++) {
            const int col = nc * 32 + nf * 8 + 2 * tt;
            if (col < EMB) {
                const int ra = r0g + wm * 32 + mf * 16 + gq;
                *(float2*)&Pp[(size_t)ra * 104 + col] =
                    make_float2(acc[mf][nf][0], acc[mf][nf][1]);
                *(float2*)&Pp[(size_t)(ra + 8) * 104 + col] =
                    make_float2(acc[mf][nf][2], acc[mf][nf][3]);
            }
        }
}

// ---------------- merge K-splits: bias + relu -> H1 + BN partials ----------
__global__ void k_merge(const float* __restrict__ bias) {
    __shared__ float Ds[64][104];
    const int t = threadIdx.x, tile = blockIdx.x, p = blockIdx.y;
    const int r = t >> 2, cg = t & 3;
    const size_t row = (size_t)tile * 64 + r;
    #pragma unroll
    for (int j = 0; j < 25; j++) {
        const int c = cg * 25 + j;
        float v = g_Part[0][p][row][c] + g_Part[1][p][row][c] + bias[c];
        v = fmaxf(v, 0.f);
        g_H1[((size_t)p * BR + row) * EMB + c] = v;
        Ds[r][c] = v;
    }
    __syncthreads();
    if (t < EMB) {
        float s = 0.f, s2 = 0.f;
        #pragma unroll 8
        for (int rr = 0; rr < 64; rr++) { float u = Ds[rr][t]; s += u; s2 += u * u; }
        g_P[0][p][tile][0][t] = s;
        g_P[0][p][tile][1][t] = s2;
    }
}

// ---------------- BN stats ----------------
__global__ void k_stats(int stage, const float* __restrict__ g,
                        const float* __restrict__ be, int ntiles)
{
    __shared__ float sred[2][2][EMB];
    const int p = blockIdx.x, t = threadIdx.x;
    const int c = t & 127, half = t >> 7;
    const int cnt = ntiles >> 1;
    if (c < EMB) {
        float a0 = 0.f, a1 = 0.f, b0 = 0.f, b1 = 0.f;
        const int base = half * cnt;
        for (int i = 0; i < cnt; i += 2) {
            a0 += g_P[stage][p][base + i][0][c];
            a1 += g_P[stage][p][base + i + 1][0][c];
            b0 += g_P[stage][p][base + i][1][c];
            b1 += g_P[stage][p][base + i + 1][1][c];
        }
        sred[half][0][c] = a0 + a1;
        sred[half][1][c] = b0 + b1;
    }
    __syncthreads();
    if (t < EMB) {
        float s1 = sred[0][0][t] + sred[1][0][t];
        float s2 = sred[0][1][t] + sred[1][1][t];
        float mu  = s1 * (1.f / BR);
        float var = s2 * (1.f / BR) - mu * mu;
        float sc  = g[t] * rsqrtf(var + EPSB);
        g_bns[stage][p][t] = sc;
        g_bnb[stage][p][t] = be[t] - mu * sc;
    }
}

// ---------------- Layers 2-4 ----------------
__global__ __launch_bounds__(256, 1)
void k_small(int layer, const float* __restrict__ W,
             const float* __restrict__ bias, float* __restrict__ dout)
{
    extern __shared__ float sm[];
    float* Hs  = sm;            // 100*33
    float* Ws  = sm + 3300;     // 100*132
    float* red = sm + 16500;    // 2048
    float* sc  = sm + 18548;
    float* sh  = sm + 18676;

    const int t = threadIdx.x, tile = blockIdx.x, p = blockIdx.y;
    const int r0 = tile * 32;
    const int ty = t >> 4, tx = t & 15;
    const float* Hin = (layer == 0) ? g_H1 : (layer == 1) ? g_H2 : g_H3;
    const bool rin = (layer == 2), rout = (layer == 0);

    if (t < EMB) { sc[t] = g_bns[layer][p][t]; sh[t] = g_bnb[layer][p][t]; }
    __syncthreads();

    const float* Hp = Hin + (size_t)p * BR * EMB;
    for (int i = t; i < 32 * EMB; i += 256) {
        int row = i / EMB, k = i % EMB;
        float v = Hp[(size_t)(r0 + row) * EMB + k] * sc[k] + sh[k];
        if (rin) v = fmaxf(v, 0.f);
        Hs[k * 33 + row] = v;
    }
    for (int i = t; i < EMB * EMB; i += 256) {
        int nn = i / EMB, k = i % EMB;
        Ws[k * 132 + nn] = W[i];
    }
    for (int i = t; i < EMB * 28; i += 256) {
        int k = i / 28, nn = 100 + i % 28;
        Ws[k * 132 + nn] = 0.f;
    }
    __syncthreads();

    u64 acc[2][4];
    #pragma unroll
    for (int r = 0; r < 2; r++)
        #pragma unroll
        for (int c = 0; c < 4; c++) acc[r][c] = 0ull;

    #pragma unroll 4
    for (int k = 0; k < EMB; k++) {
        const float* ak = Hs + k * 33 + ty * 2;
        float a0 = ak[0], a1 = ak[1];
        const u64* wp = (const u64*)(Ws + k * 132 + tx * 8);
        u64 b0 = wp[0], b1 = wp[1], b2 = wp[2], b3 = wp[3];
        u64 A0 = pk2(a0, a0), A1 = pk2(a1, a1);
        acc[0][0]=fma2(A0,b0,acc[0][0]); acc[0][1]=fma2(A0,b1,acc[0][1]);
        acc[0][2]=fma2(A0,b2,acc[0][2]); acc[0][3]=fma2(A0,b3,acc[0][3]);
        acc[1][0]=fma2(A1,b0,acc[1][0]); acc[1][1]=fma2(A1,b1,acc[1][1]);
        acc[1][2]=fma2(A1,b2,acc[1][2]); acc[1][3]=fma2(A1,b3,acc[1][3]);
    }

    float* Hout = (layer == 0) ? g_H2 : g_H3;
    float vo[2][8];
    #pragma unroll
    for (int r = 0; r < 2; r++) {
        int row = r0 + ty * 2 + r;
        #pragma unroll
        for (int cp = 0; cp < 4; cp++) {
            float2 f = upk2(acc[r][cp]);
            #pragma unroll
            for (int hh = 0; hh < 2; hh++) {
                int col = tx * 8 + cp * 2 + hh;
                float v = (hh ? f.y : f.x) + (col < EMB ? bias[col] : 0.f);
                if (rout) v = fmaxf(v, 0.f);
                vo[r][cp * 2 + hh] = v;
                if (col < EMB) {
                    if (layer == 2) dout[((size_t)p * BR + row) * EMB + col] = v;
                    else            Hout[((size_t)p * BR + row) * EMB + col] = v;
                }
            }
        }
    }
    if (layer < 2) {
        #pragma unroll
        for (int c = 0; c < 8; c++)
            red[ty * 128 + tx * 8 + c] = vo[0][c] + vo[1][c];
        __syncthreads();
        if (t < 128) {
            float s = 0.f;
            #pragma unroll
            for (int g = 0; g < 16; g++) s += red[g * 128 + t];
            if (t < EMB) g_P[layer + 1][p][tile][0][t] = s;
        }
        __syncthreads();
        #pragma unroll
        for (int c = 0; c < 8; c++)
            red[ty * 128 + tx * 8 + c] = vo[0][c]*vo[0][c] + vo[1][c]*vo[1][c];
        __syncthreads();
        if (t < 128) {
            float s = 0.f;
            #pragma unroll
            for (int g = 0; g < 16; g++) s += red[g * 128 + t];
            if (t < EMB) g_P[layer + 1][p][tile][1][t] = s;
        }
    }
}

// ---------------- launch ----------------
extern "C" void kernel_launch(void* const* d_in, const int* in_sizes, int n_in,
                              void* d_out, int out_size)
{
    const float* x   = (const float*)d_in[0];
    const void*  mk  = d_in[1];
    const float* xr  = (const float*)d_in[2];
    const float* w1  = (const float*)d_in[3];
    const float* b1  = (const float*)d_in[4];
    const float* g1  = (const float*)d_in[5];
    const float* be1 = (const float*)d_in[6];
    const float* w2  = (const float*)d_in[7];
    const float* b2  = (const float*)d_in[8];
    const float* g2  = (const float*)d_in[9];
    const float* be2 = (const float*)d_in[10];
    const float* hw1 = (const float*)d_in[11];
    const float* hb1 = (const float*)d_in[12];
    const float* hg1 = (const float*)d_in[13];
    const float* hbe1= (const float*)d_in[14];
    const float* hw2 = (const float*)d_in[15];
    const float* hb2 = (const float*)d_in[16];
    float* out = (float*)d_out;

    cudaFuncSetAttribute(k_big,   cudaFuncAttributeMaxDynamicSharedMemorySize, NSTG * STG);
    cudaFuncSetAttribute(k_small, cudaFuncAttributeMaxDynamicSharedMemorySize, 76816);

    const int H = NPAD * MF / 2 / 2;
    k_detect<<<1, 256>>>((const unsigned char*)mk);          // 1
    k_wcvt<<<(H + 255) / 256, 256>>>(w1, 0);                 // 2
    k_wcvt<<<(H + 255) / 256, 256>>>(w1, H);                 // 3
    k_big<<<256, 256, NSTG * STG>>>(x, mk, xr);              // 4 <- profiled
    k_merge<<<dim3(64, 2), 256>>>(b1);                       // 5
    k_stats<<<2, 256>>>(0, g1, be1, 64);
    k_small<<<dim3(128, 2), 256, 76816>>>(0, w2, b2, nullptr);
    k_stats<<<2, 256>>>(1, g2, be2, 128);
    k_small<<<dim3(128, 2), 256, 76816>>>(1, hw1, hb1, nullptr);
    k_stats<<<2, 256>>>(2, hg1, hbe1, 128);
    k_small<<<dim3(128, 2), 256, 76816>>>(2, hw2, hb2, out);
}

// round 10
// speedup vs baseline: 1.5218x; 1.5218x over previous
#include <cuda_runtime.h>
#include <cuda_fp16.h>
#include <cstdint>
#include <cstddef>

#define BR   4096
#define MF   20000
#define EMB  100
#define NPAD 128
#define KC   32
#define EPSB 1e-5f
#define STG  20480          // A 4K | Wh 8K | Wl 8K
#define NSTG 3
#define WSC  64.0f          // W pre-scale (epilogue multiplies by 1/64)

typedef unsigned long long u64;
typedef unsigned int u32;

// ---------------- device scratch ----------------
__device__ int   g_mode;                       // 0=int32, 1=byte bool, 2=float32
__device__ unsigned short g_Wh[NPAD * MF];     // fp16 hi of 64*W, rows 100..127 zero
__device__ unsigned short g_Wl[NPAD * MF];     // fp16 lo of 64*W
__device__ float g_Part[4][2][BR][104];        // ksplit, pass, row, col
__device__ float g_H1[2 * BR * EMB];
__device__ float g_H2[2 * BR * EMB];
__device__ float g_H3[2 * BR * EMB];
__device__ float g_P[3][2][128][2][EMB];
__device__ float g_bns[3][2][EMB];
__device__ float g_bnb[3][2][EMB];

// ---------------- helpers ----------------
__device__ __forceinline__ u32 smem_u32(const void* p) {
    u32 a; asm("{ .reg .u64 t; cvta.to.shared.u64 t, %1; cvt.u32.u64 %0, t; }" : "=r"(a) : "l"(p));
    return a;
}
__device__ __forceinline__ void ldsm4(u32& r0, u32& r1, u32& r2, u32& r3, u32 addr) {
    asm volatile("ldmatrix.sync.aligned.m8n8.x4.shared.b16 {%0,%1,%2,%3}, [%4];"
        : "=r"(r0), "=r"(r1), "=r"(r2), "=r"(r3) : "r"(addr));
}
__device__ __forceinline__ void mma16816(float* d, const u32* a, const u32* b) {
    asm volatile("mma.sync.aligned.m16n8k16.row.col.f32.f16.f16.f32 "
        "{%0,%1,%2,%3}, {%4,%5,%6,%7}, {%8,%9}, {%0,%1,%2,%3};"
        : "+f"(d[0]), "+f"(d[1]), "+f"(d[2]), "+f"(d[3])
        : "r"(a[0]), "r"(a[1]), "r"(a[2]), "r"(a[3]), "r"(b[0]), "r"(b[1]));
}
__device__ __forceinline__ void cp16(u32 dst, const void* src) {
    asm volatile("cp.async.cg.shared.global [%0], [%1], 16;"
        :: "r"(dst), "l"(src) : "memory");
}
#define CP_COMMIT() asm volatile("cp.async.commit_group;" ::: "memory")
#define CP_WAIT1()  asm volatile("cp.async.wait_group 1;" ::: "memory")
#define CP_WAIT0()  asm volatile("cp.async.wait_group 0;" ::: "memory")

// 64B-row swizzle
__device__ __forceinline__ u32 sw64(u32 row, u32 colb) {
    return row * 64 + (colb ^ (((row >> 1) & 3) << 4));
}
// fp16x2 pack: element0 -> low half, element1 -> high half
__device__ __forceinline__ u32 pk_f16(float lo, float hi) {
    u32 r; asm("cvt.rn.f16x2.f32 %0, %1, %2;" : "=r"(r) : "f"(hi), "f"(lo));
    return r;
}
// packed f32x2 (small layers)
__device__ __forceinline__ u64 pk2(float lo, float hi) {
    u64 d; asm("mov.b64 %0, {%1, %2};" : "=l"(d) : "f"(lo), "f"(hi)); return d;
}
__device__ __forceinline__ u64 fma2(u64 a, u64 b, u64 c) {
    u64 d; asm("fma.rn.f32x2 %0, %1, %2, %3;" : "=l"(d) : "l"(a), "l"(b), "l"(c)); return d;
}
__device__ __forceinline__ float2 upk2(u64 v) {
    float2 r; asm("mov.b64 {%0, %1}, %2;" : "=f"(r.x), "=f"(r.y) : "l"(v)); return r;
}

// ---------------- mask dtype classifier ----------------
__global__ void k_detect(const unsigned char* __restrict__ m) {
    __shared__ int s_nz, s_gt;
    if (threadIdx.x == 0) { s_nz = 0; s_gt = 0; }
    __syncthreads();
    int nz = 0, gt = 0;
    for (int i = threadIdx.x; i < 65536; i += blockDim.x) {
        unsigned char v = m[i];
        nz += (v != 0); gt += (v > 1);
    }
    atomicAdd(&s_nz, nz); atomicAdd(&s_gt, gt);
    __syncthreads();
    if (threadIdx.x == 0)
        g_mode = (s_gt > 64) ? 2 : (s_nz > 24576) ? 1 : 0;
}

// ---------------- W split precompute: 64*W = Wh + Wl (fp16) ----------------
__global__ void k_wcvt(const float* __restrict__ w, int base) {
    int i = base + blockIdx.x * blockDim.x + threadIdx.x;
    if (i >= NPAD * MF / 2) return;
    int row = i / (MF / 2), within = i % (MF / 2);
    if (row < EMB) {
        float2 v = *(const float2*)(w + (size_t)row * MF + 2 * within);
        float sx = WSC * v.x, sy = WSC * v.y;
        float hx = __half2float(__float2half_rn(sx));
        float hy = __half2float(__float2half_rn(sy));
        ((u32*)g_Wh)[i] = pk_f16(hx, hy);
        ((u32*)g_Wl)[i] = pk_f16(sx - hx, sy - hy);
    } else {
        ((u32*)g_Wh)[i] = 0u;
        ((u32*)g_Wl)[i] = 0u;
    }
}

// ---------------- Layer 1: 2-term fp16 mma.sync, 3-stage, 3 CTAs/SM --------
// grid=512: p = bid&1, ks4 = (bid>>1)&3, tile = bid>>3 (64 rows).
// Stage (20KB): A@0 4K | Wh@4K 8K | Wl@12K 8K. 64B rows (KC=32 fp16).
__global__ __launch_bounds__(256, 3)
void k_big(const float* __restrict__ x, const void* __restrict__ mk,
           const float* __restrict__ xr)
{
    extern __shared__ char smem[];
    const u32 sb = smem_u32(smem);
    const int t = threadIdx.x;
    const int w = t >> 5, lane = t & 31;
    const int p = blockIdx.x & 1, ks4 = (blockIdx.x >> 1) & 3, tile = blockIdx.x >> 3;
    const int r0g = tile * 64;
    const int ci0 = ks4 ? (157 + 156 * (ks4 - 1)) : 0;
    const int n   = ks4 ? 156 : 157;
    const int wm = w >> 2, nc = w & 3;
    const int mode = g_mode;

    // A staging: one 16B store per thread: arow = t>>2, seg = t&3
    const int arow = t >> 2, seg = t & 3;
    const size_t abase = (size_t)(r0g + arow) * MF + (size_t)(ci0 * KC) + seg * 8;
    const u32 aoff = sw64(arow, seg * 16);

    // W cp.async: 2 chunks of 16B per thread per split
    u32 woff0, woff1; size_t wsrc0, wsrc1;
    {
        int g0 = t, g1 = t + 256;
        int r0w = g0 >> 2, s0 = g0 & 3, r1w = g1 >> 2, s1 = g1 & 3;
        woff0 = sw64(r0w, s0 * 16);
        woff1 = sw64(r1w, s1 * 16);
        wsrc0 = (size_t)r0w * MF + (size_t)(ci0 * KC) + s0 * 8;
        wsrc1 = (size_t)r1w * MF + (size_t)(ci0 * KC) + s1 * 8;
    }

    uint4 HA;
    float acc[2][4][4];
    #pragma unroll
    for (int mf = 0; mf < 2; mf++)
        #pragma unroll
        for (int nf = 0; nf < 4; nf++)
            #pragma unroll
            for (int e = 0; e < 4; e++) acc[mf][nf][e] = 0.f;

    auto CPW = [&](int j) {           // local chunk j -> stage j%3
        const u32 base = sb + (j % 3) * STG;
        const size_t ko = (size_t)j * KC;
        cp16(base +  4096 + woff0, g_Wh + wsrc0 + ko);
        cp16(base +  4096 + woff1, g_Wh + wsrc1 + ko);
        cp16(base + 12288 + woff0, g_Wl + wsrc0 + ko);
        cp16(base + 12288 + woff1, g_Wl + wsrc1 + ko);
    };

    auto STAGE = [&](int j) {
        const size_t g = abase + (size_t)j * KC;
        float v[8];
        float4 x0 = *(const float4*)(x + g);
        float4 x1 = *(const float4*)(x + g + 4);
        v[0]=x0.x; v[1]=x0.y; v[2]=x0.z; v[3]=x0.w;
        v[4]=x1.x; v[5]=x1.y; v[6]=x1.z; v[7]=x1.w;
        if (p == 1) {
            float4 q0 = *(const float4*)(xr + g);
            float4 q1 = *(const float4*)(xr + g + 4);
            float q[8] = {q0.x,q0.y,q0.z,q0.w,q1.x,q1.y,q1.z,q1.w};
            if (mode == 1) {
                uint2 mm = *(const uint2*)((const unsigned char*)mk + g);
                u32 lo = mm.x, hi = mm.y;
                #pragma unroll
                for (int m = 0; m < 4; m++) {
                    if ((lo >> (m*8)) & 0xff) v[m]   = q[m];
                    if ((hi >> (m*8)) & 0xff) v[m+4] = q[m+4];
                }
            } else if (mode == 0) {
                int4 m0 = *(const int4*)((const int*)mk + g);
                int4 m1 = *(const int4*)((const int*)mk + g + 4);
                int mi[8] = {m0.x,m0.y,m0.z,m0.w,m1.x,m1.y,m1.z,m1.w};
                #pragma unroll
                for (int m = 0; m < 8; m++) if (mi[m]) v[m] = q[m];
            } else {
                float4 m0 = *(const float4*)((const float*)mk + g);
                float4 m1 = *(const float4*)((const float*)mk + g + 4);
                float mf_[8] = {m0.x,m0.y,m0.z,m0.w,m1.x,m1.y,m1.z,m1.w};
                #pragma unroll
                for (int m = 0; m < 8; m++) if (mf_[m] != 0.f) v[m] = q[m];
            }
        }
        HA.x = pk_f16(v[0],v[1]); HA.y = pk_f16(v[2],v[3]);
        HA.z = pk_f16(v[4],v[5]); HA.w = pk_f16(v[6],v[7]);
    };

    auto STORE_A = [&](int j) {
        char* bs = smem + (j % 3) * STG;
        *(uint4*)(bs + aoff) = HA;
    };

    // COMP lane addressing
    const u32 rowa = wm * 32 + (lane & 15);
    const u32 c16A = ((lane >> 4) & 1) * 16;
    const u32 xrA  = ((rowa >> 1) & 3) << 4;
    const u32 baseA0 = rowa * 64;
    const u32 baseA1 = (rowa + 16) * 64;
    const u32 xrA1 = (((rowa + 16) >> 1) & 3) << 4;
    const u32 nrow = nc * 32 + ((lane >> 4) & 1) * 8 + (lane & 7);
    const u32 c16B = ((lane >> 3) & 1) * 16;
    const u32 baseB0 = nrow * 64,        xrB0 = ((nrow >> 1) & 3) << 4;
    const u32 baseB1 = (nrow + 16) * 64, xrB1 = (((nrow + 16) >> 1) & 3) << 4;

    auto COMP = [&](int j) {
        const u32 bs = sb + (j % 3) * STG;
        const u32 Ab = bs, Wh = bs + 4096, Wl = bs + 12288;
        #pragma unroll
        for (int ks = 0; ks < 2; ks++) {
            const u32 kb = ks * 32;
            u32 aF[2][4], bH[4][2], bL[4][2];
            ldsm4(aF[0][0], aF[0][1], aF[0][2], aF[0][3], Ab + baseA0 + ((kb + c16A) ^ xrA));
            ldsm4(aF[1][0], aF[1][1], aF[1][2], aF[1][3], Ab + baseA1 + ((kb + c16A) ^ xrA1));
            ldsm4(bH[0][0], bH[0][1], bH[1][0], bH[1][1], Wh + baseB0 + ((kb + c16B) ^ xrB0));
            ldsm4(bH[2][0], bH[2][1], bH[3][0], bH[3][1], Wh + baseB1 + ((kb + c16B) ^ xrB1));
            ldsm4(bL[0][0], bL[0][1], bL[1][0], bL[1][1], Wl + baseB0 + ((kb + c16B) ^ xrB0));
            ldsm4(bL[2][0], bL[2][1], bL[3][0], bL[3][1], Wl + baseB1 + ((kb + c16B) ^ xrB1));
            #pragma unroll
            for (int mf = 0; mf < 2; mf++)
                #pragma unroll
                for (int nf = 0; nf < 4; nf++) {
                    mma16816(acc[mf][nf], aF[mf], bH[nf]);
                    mma16816(acc[mf][nf], aF[mf], bL[nf]);
                }
        }
    };

    // prologue
    CPW(0); CP_COMMIT();
    CPW(1); CP_COMMIT();
    STAGE(0);
    CP_WAIT1();                  // W(0) arrived
    STORE_A(0);
    __syncthreads();
    STAGE(1);

    for (int i = 0; i < n; i++) {
        if (i + 1 < n) STORE_A(i + 1);    // HA staged at end of prev iter
        COMP(i);
        if (i + 2 < n) { CPW(i + 2); CP_COMMIT(); CP_WAIT1(); }
        else if (i + 1 < n) CP_WAIT0();
        __syncthreads();
        if (i + 2 < n) STAGE(i + 2);
    }

    // epilogue: raw partials (scaled by 64) -> g_Part
    float* Pp = &g_Part[ks4][p][0][0];
    const int gq = lane >> 2, tt = lane & 3;
    #pragma unroll
    for (int mf = 0; mf < 2; mf++)
        #pragma unroll
        for (int nf = 0; nf < 4; nf++) {
            const int col = nc * 32 + nf * 8 + 2 * tt;
            if (col < EMB) {
                const int ra = r0g + wm * 32 + mf * 16 + gq;
                *(float2*)&Pp[(size_t)ra * 104 + col] =
                    make_float2(acc[mf][nf][0], acc[mf][nf][1]);
                *(float2*)&Pp[(size_t)(ra + 8) * 104 + col] =
                    make_float2(acc[mf][nf][2], acc[mf][nf][3]);
            }
        }
}

// ---------------- merge K-splits: unscale + bias + relu -> H1 + partials ---
__global__ void k_merge(const float* __restrict__ bias) {
    __shared__ float Ds[64][104];
    const int t = threadIdx.x, tile = blockIdx.x, p = blockIdx.y;
    const int r = t >> 2, cg = t & 3;
    const size_t row = (size_t)tile * 64 + r;
    #pragma unroll
    for (int j = 0; j < 25; j++) {
        const int c = cg * 25 + j;
        float v = (g_Part[0][p][row][c] + g_Part[1][p][row][c]
                 + g_Part[2][p][row][c] + g_Part[3][p][row][c]) * (1.0f / WSC)
                 + bias[c];
        v = fmaxf(v, 0.f);
        g_H1[((size_t)p * BR + row) * EMB + c] = v;
        Ds[r][c] = v;
    }
    __syncthreads();
    if (t < EMB) {
        float s = 0.f, s2 = 0.f;
        #pragma unroll 8
        for (int rr = 0; rr < 64; rr++) { float u = Ds[rr][t]; s += u; s2 += u * u; }
        g_P[0][p][tile][0][t] = s;
        g_P[0][p][tile][1][t] = s2;
    }
}

// ---------------- BN stats ----------------
__global__ void k_stats(int stage, const float* __restrict__ g,
                        const float* __restrict__ be, int ntiles)
{
    __shared__ float sred[2][2][EMB];
    const int p = blockIdx.x, t = threadIdx.x;
    const int c = t & 127, half = t >> 7;
    const int cnt = ntiles >> 1;
    if (c < EMB) {
        float a0 = 0.f, a1 = 0.f, b0 = 0.f, b1 = 0.f;
        const int base = half * cnt;
        for (int i = 0; i < cnt; i += 2) {
            a0 += g_P[stage][p][base + i][0][c];
            a1 += g_P[stage][p][base + i + 1][0][c];
            b0 += g_P[stage][p][base + i][1][c];
            b1 += g_P[stage][p][base + i + 1][1][c];
        }
        sred[half][0][c] = a0 + a1;
        sred[half][1][c] = b0 + b1;
    }
    __syncthreads();
    if (t < EMB) {
        float s1 = sred[0][0][t] + sred[1][0][t];
        float s2 = sred[0][1][t] + sred[1][1][t];
        float mu  = s1 * (1.f / BR);
        float var = s2 * (1.f / BR) - mu * mu;
        float sc  = g[t] * rsqrtf(var + EPSB);
        g_bns[stage][p][t] = sc;
        g_bnb[stage][p][t] = be[t] - mu * sc;
    }
}

// ---------------- Layers 2-4 ----------------
__global__ __launch_bounds__(256, 1)
void k_small(int layer, const float* __restrict__ W,
             const float* __restrict__ bias, float* __restrict__ dout)
{
    extern __shared__ float sm[];
    float* Hs  = sm;            // 100*33
    float* Ws  = sm + 3300;     // 100*132
    float* red = sm + 16500;    // 2048
    float* sc  = sm + 18548;
    float* sh  = sm + 18676;

    const int t = threadIdx.x, tile = blockIdx.x, p = blockIdx.y;
    const int r0 = tile * 32;
    const int ty = t >> 4, tx = t & 15;
    const float* Hin = (layer == 0) ? g_H1 : (layer == 1) ? g_H2 : g_H3;
    const bool rin = (layer == 2), rout = (layer == 0);

    if (t < EMB) { sc[t] = g_bns[layer][p][t]; sh[t] = g_bnb[layer][p][t]; }
    __syncthreads();

    const float* Hp = Hin + (size_t)p * BR * EMB;
    for (int i = t; i < 32 * EMB; i += 256) {
        int row = i / EMB, k = i % EMB;
        float v = Hp[(size_t)(r0 + row) * EMB + k] * sc[k] + sh[k];
        if (rin) v = fmaxf(v, 0.f);
        Hs[k * 33 + row] = v;
    }
    for (int i = t; i < EMB * EMB; i += 256) {
        int nn = i / EMB, k = i % EMB;
        Ws[k * 132 + nn] = W[i];
    }
    for (int i = t; i < EMB * 28; i += 256) {
        int k = i / 28, nn = 100 + i % 28;
        Ws[k * 132 + nn] = 0.f;
    }
    __syncthreads();

    u64 acc[2][4];
    #pragma unroll
    for (int r = 0; r < 2; r++)
        #pragma unroll
        for (int c = 0; c < 4; c++) acc[r][c] = 0ull;

    #pragma unroll 4
    for (int k = 0; k < EMB; k++) {
        const float* ak = Hs + k * 33 + ty * 2;
        float a0 = ak[0], a1 = ak[1];
        const u64* wp = (const u64*)(Ws + k * 132 + tx * 8);
        u64 b0 = wp[0], b1 = wp[1], b2 = wp[2], b3 = wp[3];
        u64 A0 = pk2(a0, a0), A1 = pk2(a1, a1);
        acc[0][0]=fma2(A0,b0,acc[0][0]); acc[0][1]=fma2(A0,b1,acc[0][1]);
        acc[0][2]=fma2(A0,b2,acc[0][2]); acc[0][3]=fma2(A0,b3,acc[0][3]);
        acc[1][0]=fma2(A1,b0,acc[1][0]); acc[1][1]=fma2(A1,b1,acc[1][1]);
        acc[1][2]=fma2(A1,b2,acc[1][2]); acc[1][3]=fma2(A1,b3,acc[1][3]);
    }

    float* Hout = (layer == 0) ? g_H2 : g_H3;
    float vo[2][8];
    #pragma unroll
    for (int r = 0; r < 2; r++) {
        int row = r0 + ty * 2 + r;
        #pragma unroll
        for (int cp = 0; cp < 4; cp++) {
            float2 f = upk2(acc[r][cp]);
            #pragma unroll
            for (int hh = 0; hh < 2; hh++) {
                int col = tx * 8 + cp * 2 + hh;
                float v = (hh ? f.y : f.x) + (col < EMB ? bias[col] : 0.f);
                if (rout) v = fmaxf(v, 0.f);
                vo[r][cp * 2 + hh] = v;
                if (col < EMB) {
                    if (layer == 2) dout[((size_t)p * BR + row) * EMB + col] = v;
                    else            Hout[((size_t)p * BR + row) * EMB + col] = v;
                }
            }
        }
    }
    if (layer < 2) {
        #pragma unroll
        for (int c = 0; c < 8; c++)
            red[ty * 128 + tx * 8 + c] = vo[0][c] + vo[1][c];
        __syncthreads();
        if (t < 128) {
            float s = 0.f;
            #pragma unroll
            for (int g = 0; g < 16; g++) s += red[g * 128 + t];
            if (t < EMB) g_P[layer + 1][p][tile][0][t] = s;
        }
        __syncthreads();
        #pragma unroll
        for (int c = 0; c < 8; c++)
            red[ty * 128 + tx * 8 + c] = vo[0][c]*vo[0][c] + vo[1][c]*vo[1][c];
        __syncthreads();
        if (t < 128) {
            float s = 0.f;
            #pragma unroll
            for (int g = 0; g < 16; g++) s += red[g * 128 + t];
            if (t < EMB) g_P[layer + 1][p][tile][1][t] = s;
        }
    }
}

// ---------------- launch ----------------
extern "C" void kernel_launch(void* const* d_in, const int* in_sizes, int n_in,
                              void* d_out, int out_size)
{
    const float* x   = (const float*)d_in[0];
    const void*  mk  = d_in[1];
    const float* xr  = (const float*)d_in[2];
    const float* w1  = (const float*)d_in[3];
    const float* b1  = (const float*)d_in[4];
    const float* g1  = (const float*)d_in[5];
    const float* be1 = (const float*)d_in[6];
    const float* w2  = (const float*)d_in[7];
    const float* b2  = (const float*)d_in[8];
    const float* g2  = (const float*)d_in[9];
    const float* be2 = (const float*)d_in[10];
    const float* hw1 = (const float*)d_in[11];
    const float* hb1 = (const float*)d_in[12];
    const float* hg1 = (const float*)d_in[13];
    const float* hbe1= (const float*)d_in[14];
    const float* hw2 = (const float*)d_in[15];
    const float* hb2 = (const float*)d_in[16];
    float* out = (float*)d_out;

    cudaFuncSetAttribute(k_big,   cudaFuncAttributeMaxDynamicSharedMemorySize, NSTG * STG);
    cudaFuncSetAttribute(k_small, cudaFuncAttributeMaxDynamicSharedMemorySize, 76816);

    const int H = NPAD * MF / 2 / 2;
    k_detect<<<1, 256>>>((const unsigned char*)mk);          // 1
    k_wcvt<<<(H + 255) / 256, 256>>>(w1, 0);                 // 2
    k_wcvt<<<(H + 255) / 256, 256>>>(w1, H);                 // 3
    k_big<<<512, 256, NSTG * STG>>>(x, mk, xr);              // 4 <- profiled
    k_merge<<<dim3(64, 2), 256>>>(b1);                       // 5
    k_stats<<<2, 256>>>(0, g1, be1, 64);
    k_small<<<dim3(128, 2), 256, 76816>>>(0, w2, b2, nullptr);
    k_stats<<<2, 256>>>(1, g2, be2, 128);
    k_small<<<dim3(128, 2), 256, 76816>>>(1, hw1, hb1, nullptr);
    k_stats<<<2, 256>>>(2, hg1, hbe1, 128);
    k_small<<<dim3(128, 2), 256, 76816>>>(2, hw2, hb2, out);
}

// round 11
// speedup vs baseline: 1.6493x; 1.0838x over previous
#include <cuda_runtime.h>
#include <cuda_fp16.h>
#include <cstdint>
#include <cstddef>

#define BR    4096
#define MF    20000
#define EMB   100
#define WROWS 104           // trimmed W rows (100 real + 4 zero)
#define KC    32
#define KSPL  5
#define KPER  4000          // k per split = 125 * 32 exactly
#define NCHS  125
#define EPSB  1e-5f
#define STG   18432         // A0 2K | A1 2K | Wh 7K | Wl 7K
#define NSTG  3
#define WSC   64.0f

typedef unsigned long long u64;
typedef unsigned int u32;

// ---------------- device scratch ----------------
__device__ int   g_mode;                       // 0=int32, 1=byte bool, 2=float32
__device__ unsigned short g_Wh[WROWS * MF];    // fp16 hi of 64*W, rows 100..103 zero
__device__ unsigned short g_Wl[WROWS * MF];    // fp16 lo of 64*W
__device__ float g_Part[KSPL][2][BR][104];     // ksplit, pass, row, col
__device__ float g_H1[2 * BR * EMB];
__device__ float g_H2[2 * BR * EMB];
__device__ float g_H3[2 * BR * EMB];
__device__ float g_P[3][2][128][2][EMB];       // stage, pass, tile, {sum,sumsq}, col
__device__ float g_bns_unused[4];              // (kept layout simple)

// ---------------- helpers ----------------
__device__ __forceinline__ u32 smem_u32(const void* p) {
    u32 a; asm("{ .reg .u64 t; cvta.to.shared.u64 t, %1; cvt.u32.u64 %0, t; }" : "=r"(a) : "l"(p));
    return a;
}
__device__ __forceinline__ void ldsm4(u32& r0, u32& r1, u32& r2, u32& r3, u32 addr) {
    asm volatile("ldmatrix.sync.aligned.m8n8.x4.shared.b16 {%0,%1,%2,%3}, [%4];"
        : "=r"(r0), "=r"(r1), "=r"(r2), "=r"(r3) : "r"(addr));
}
__device__ __forceinline__ void mma16816(float* d, const u32* a, const u32* b) {
    asm volatile("mma.sync.aligned.m16n8k16.row.col.f32.f16.f16.f32 "
        "{%0,%1,%2,%3}, {%4,%5,%6,%7}, {%8,%9}, {%0,%1,%2,%3};"
        : "+f"(d[0]), "+f"(d[1]), "+f"(d[2]), "+f"(d[3])
        : "r"(a[0]), "r"(a[1]), "r"(a[2]), "r"(a[3]), "r"(b[0]), "r"(b[1]));
}
__device__ __forceinline__ void cp16(u32 dst, const void* src) {
    asm volatile("cp.async.cg.shared.global [%0], [%1], 16;"
        :: "r"(dst), "l"(src) : "memory");
}
#define CP_COMMIT() asm volatile("cp.async.commit_group;" ::: "memory")
#define CP_WAIT1()  asm volatile("cp.async.wait_group 1;" ::: "memory")
#define CP_WAIT0()  asm volatile("cp.async.wait_group 0;" ::: "memory")

// 64B-row swizzle
__device__ __forceinline__ u32 sw64(u32 row, u32 colb) {
    return row * 64 + (colb ^ (((row >> 1) & 3) << 4));
}
// fp16x2 pack: element0 -> low half, element1 -> high half
__device__ __forceinline__ u32 pk_f16(float lo, float hi) {
    u32 r; asm("cvt.rn.f16x2.f32 %0, %1, %2;" : "=r"(r) : "f"(hi), "f"(lo));
    return r;
}
// packed f32x2 (small layers)
__device__ __forceinline__ u64 pk2(float lo, float hi) {
    u64 d; asm("mov.b64 %0, {%1, %2};" : "=l"(d) : "f"(lo), "f"(hi)); return d;
}
__device__ __forceinline__ u64 fma2(u64 a, u64 b, u64 c) {
    u64 d; asm("fma.rn.f32x2 %0, %1, %2, %3;" : "=l"(d) : "l"(a), "l"(b), "l"(c)); return d;
}
__device__ __forceinline__ float2 upk2(u64 v) {
    float2 r; asm("mov.b64 {%0, %1}, %2;" : "=f"(r.x), "=f"(r.y) : "l"(v)); return r;
}

// ---------------- mask dtype classifier ----------------
__global__ void k_detect(const unsigned char* __restrict__ m) {
    __shared__ int s_nz, s_gt;
    if (threadIdx.x == 0) { s_nz = 0; s_gt = 0; }
    __syncthreads();
    int nz = 0, gt = 0;
    for (int i = threadIdx.x; i < 65536; i += blockDim.x) {
        unsigned char v = m[i];
        nz += (v != 0); gt += (v > 1);
    }
    atomicAdd(&s_nz, nz); atomicAdd(&s_gt, gt);
    __syncthreads();
    if (threadIdx.x == 0)
        g_mode = (s_gt > 64) ? 2 : (s_nz > 24576) ? 1 : 0;
}

// ---------------- W split precompute: 64*W = Wh + Wl (fp16, 104 rows) ------
__global__ void k_wcvt(const float* __restrict__ w, int base) {
    int i = base + blockIdx.x * blockDim.x + threadIdx.x;   // pair index
    if (i >= WROWS * MF / 2) return;
    int row = i / (MF / 2), within = i % (MF / 2);
    if (row < EMB) {
        float2 v = *(const float2*)(w + (size_t)row * MF + 2 * within);
        float sx = WSC * v.x, sy = WSC * v.y;
        float hx = __half2float(__float2half_rn(sx));
        float hy = __half2float(__float2half_rn(sy));
        ((u32*)g_Wh)[i] = pk_f16(hx, hy);
        ((u32*)g_Wl)[i] = pk_f16(sx - hx, sy - hy);
    } else {
        ((u32*)g_Wh)[i] = 0u;
        ((u32*)g_Wl)[i] = 0u;
    }
}

// ---------------- Layer 1: 2-term fp16 mma.sync, both passes per CTA -------
// grid = 640: tile = bid/5 (32 rows), ks = bid%5 (k range of 4000, 125 chunks).
// Stage (18KB): A0@0 2K | A1@2K 2K | Wh@4K 7K | Wl@11264 7K (112 rows, 104 live).
// Warps: pass = w>>2, nc = w&3 (N cols nc*32.., nc3 covers 96..111).
__global__ __launch_bounds__(256, 3)
void k_big(const float* __restrict__ x, const void* __restrict__ mk,
           const float* __restrict__ xr)
{
    extern __shared__ char smem[];
    const u32 sb = smem_u32(smem);
    const int t = threadIdx.x;
    const int w = t >> 5, lane = t & 31;
    const int tile = blockIdx.x / KSPL, ks = blockIdx.x % KSPL;
    const int r0g = tile * 32;
    const size_t k0g = (size_t)ks * KPER;
    const int pa = w >> 2, nc = w & 3;
    const int mode = g_mode;

    // A staging: half-CTA per pass; arow = (t&127)>>2, seg = t&3
    const int ph = t >> 7;
    const int arow = (t & 127) >> 2, seg = t & 3;
    const size_t abase = (size_t)(r0g + arow) * MF + k0g + (size_t)seg * 8;
    const u32 aoff = ph * 2048 + sw64(arow, seg * 16);

    // W cp.async map: up to 2 units of (row, seg) per thread per matrix
    const int gi1 = t + 256;
    const bool w1v = (gi1 < 416);              // 104 rows * 4 segs
    const int wr0 = t >> 2, wsg0 = t & 3;
    const int wr1 = gi1 >> 2, wsg1 = gi1 & 3;
    const u32 woff0 = sw64(wr0, wsg0 * 16);
    const u32 woff1 = sw64(wr1, wsg1 * 16);
    const size_t wsrc0 = (size_t)wr0 * MF + k0g + (size_t)wsg0 * 8;
    const size_t wsrc1 = (size_t)wr1 * MF + k0g + (size_t)wsg1 * 8;

    uint4 HA;
    float acc[2][4][4];
    #pragma unroll
    for (int mf = 0; mf < 2; mf++)
        #pragma unroll
        for (int nf = 0; nf < 4; nf++)
            #pragma unroll
            for (int e = 0; e < 4; e++) acc[mf][nf][e] = 0.f;

    // zero W pad rows 104..111 in all 3 stages (cp.async never writes them)
    if (t < 192) {
        const int stg_i = t / 64, rem = t % 64;
        const int mat = rem >> 5, rr = 104 + ((rem & 31) >> 2), s = rem & 3;
        *(uint4*)(smem + stg_i * STG + 4096 + mat * 7168 + sw64(rr, s * 16)) =
            make_uint4(0, 0, 0, 0);
    }

    auto CPW = [&](int j) {
        const u32 base = sb + (j % 3) * STG;
        const size_t ko = (size_t)j * KC;
        cp16(base +  4096 + woff0, g_Wh + wsrc0 + ko);
        cp16(base + 11264 + woff0, g_Wl + wsrc0 + ko);
        if (w1v) {
            cp16(base +  4096 + woff1, g_Wh + wsrc1 + ko);
            cp16(base + 11264 + woff1, g_Wl + wsrc1 + ko);
        }
    };

    auto STAGE = [&](int j) {
        const size_t g = abase + (size_t)j * KC;
        float v[8];
        float4 x0 = *(const float4*)(x + g);
        float4 x1 = *(const float4*)(x + g + 4);
        v[0]=x0.x; v[1]=x0.y; v[2]=x0.z; v[3]=x0.w;
        v[4]=x1.x; v[5]=x1.y; v[6]=x1.z; v[7]=x1.w;
        if (ph == 1) {
            float4 q0 = *(const float4*)(xr + g);
            float4 q1 = *(const float4*)(xr + g + 4);
            float q[8] = {q0.x,q0.y,q0.z,q0.w,q1.x,q1.y,q1.z,q1.w};
            if (mode == 1) {
                uint2 mm = *(const uint2*)((const unsigned char*)mk + g);
                u32 lo = mm.x, hi = mm.y;
                #pragma unroll
                for (int m = 0; m < 4; m++) {
                    if ((lo >> (m*8)) & 0xff) v[m]   = q[m];
                    if ((hi >> (m*8)) & 0xff) v[m+4] = q[m+4];
                }
            } else if (mode == 0) {
                int4 m0 = *(const int4*)((const int*)mk + g);
                int4 m1 = *(const int4*)((const int*)mk + g + 4);
                int mi[8] = {m0.x,m0.y,m0.z,m0.w,m1.x,m1.y,m1.z,m1.w};
                #pragma unroll
                for (int m = 0; m < 8; m++) if (mi[m]) v[m] = q[m];
            } else {
                float4 m0 = *(const float4*)((const float*)mk + g);
                float4 m1 = *(const float4*)((const float*)mk + g + 4);
                float mf_[8] = {m0.x,m0.y,m0.z,m0.w,m1.x,m1.y,m1.z,m1.w};
                #pragma unroll
                for (int m = 0; m < 8; m++) if (mf_[m] != 0.f) v[m] = q[m];
            }
        }
        HA.x = pk_f16(v[0],v[1]); HA.y = pk_f16(v[2],v[3]);
        HA.z = pk_f16(v[4],v[5]); HA.w = pk_f16(v[6],v[7]);
    };

    auto STORE_A = [&](int j) {
        *(uint4*)(smem + (j % 3) * STG + aoff) = HA;
    };

    // COMP lane addressing
    const u32 rA0 = lane & 15, rA1 = rA0 + 16;
    const u32 c16A = ((lane >> 4) & 1) * 16;
    const u32 baseA0 = rA0 * 64, xrA0 = ((rA0 >> 1) & 3) << 4;
    const u32 baseA1 = rA1 * 64, xrA1 = ((rA1 >> 1) & 3) << 4;
    const u32 nrow = nc * 32 + ((lane >> 4) & 1) * 8 + (lane & 7);
    const u32 c16B = ((lane >> 3) & 1) * 16;
    const u32 baseB0 = nrow * 64,        xrB0 = ((nrow >> 1) & 3) << 4;
    const u32 baseB1 = (nrow + 16) * 64, xrB1 = (((nrow + 16) >> 1) & 3) << 4;

    auto COMP = [&](int j) {
        const u32 bs = sb + (j % 3) * STG;
        const u32 Ab = bs + pa * 2048, Wh = bs + 4096, Wl = bs + 11264;
        #pragma unroll
        for (int kss = 0; kss < 2; kss++) {
            const u32 kb = kss * 32;
            u32 aF[2][4];
            ldsm4(aF[0][0], aF[0][1], aF[0][2], aF[0][3], Ab + baseA0 + ((kb + c16A) ^ xrA0));
            ldsm4(aF[1][0], aF[1][1], aF[1][2], aF[1][3], Ab + baseA1 + ((kb + c16A) ^ xrA1));
            if (nc < 3) {
                u32 bH[4][2], bL[4][2];
                ldsm4(bH[0][0], bH[0][1], bH[1][0], bH[1][1], Wh + baseB0 + ((kb + c16B) ^ xrB0));
                ldsm4(bH[2][0], bH[2][1], bH[3][0], bH[3][1], Wh + baseB1 + ((kb + c16B) ^ xrB1));
                ldsm4(bL[0][0], bL[0][1], bL[1][0], bL[1][1], Wl + baseB0 + ((kb + c16B) ^ xrB0));
                ldsm4(bL[2][0], bL[2][1], bL[3][0], bL[3][1], Wl + baseB1 + ((kb + c16B) ^ xrB1));
                #pragma unroll
                for (int mf = 0; mf < 2; mf++)
                    #pragma unroll
                    for (int nf = 0; nf < 4; nf++) {
                        mma16816(acc[mf][nf], aF[mf], bH[nf]);
                        mma16816(acc[mf][nf], aF[mf], bL[nf]);
                    }
            } else {
                u32 bH[2][2], bL[2][2];
                ldsm4(bH[0][0], bH[0][1], bH[1][0], bH[1][1], Wh + baseB0 + ((kb + c16B) ^ xrB0));
                ldsm4(bL[0][0], bL[0][1], bL[1][0], bL[1][1], Wl + baseB0 + ((kb + c16B) ^ xrB0));
                #pragma unroll
                for (int mf = 0; mf < 2; mf++)
                    #pragma unroll
                    for (int nf = 0; nf < 2; nf++) {
                        mma16816(acc[mf][nf], aF[mf], bH[nf]);
                        mma16816(acc[mf][nf], aF[mf], bL[nf]);
                    }
            }
        }
    };

    // prologue
    CPW(0); CP_COMMIT();
    CPW(1); CP_COMMIT();
    STAGE(0);
    CP_WAIT1();
    STORE_A(0);
    __syncthreads();
    STAGE(1);

    for (int i = 0; i < NCHS; i++) {
        if (i + 1 < NCHS) STORE_A(i + 1);
        COMP(i);
        if (i + 2 < NCHS) { CPW(i + 2); CP_COMMIT(); CP_WAIT1(); }
        else if (i + 1 < NCHS) CP_WAIT0();
        __syncthreads();
        if (i + 2 < NCHS) STAGE(i + 2);
    }

    // epilogue: raw partials (scaled by 64) -> g_Part[ks][pa]
    float* Pp = &g_Part[ks][pa][0][0];
    const int gq = lane >> 2, tt = lane & 3;
    #pragma unroll
    for (int mf = 0; mf < 2; mf++)
        #pragma unroll
        for (int nf = 0; nf < 4; nf++) {
            const int col = nc * 32 + nf * 8 + 2 * tt;
            if (col < EMB) {
                const int ra = r0g + mf * 16 + gq;
                *(float2*)&Pp[(size_t)ra * 104 + col] =
                    make_float2(acc[mf][nf][0], acc[mf][nf][1]);
                *(float2*)&Pp[(size_t)(ra + 8) * 104 + col] =
                    make_float2(acc[mf][nf][2], acc[mf][nf][3]);
            }
        }
}

// ---------------- merge K-splits: unscale + bias + relu -> H1 + partials ---
__global__ void k_merge(const float* __restrict__ bias) {
    __shared__ float Ds[64][104];
    const int t = threadIdx.x, tile = blockIdx.x, p = blockIdx.y;
    const int r = t >> 2, cg = t & 3;
    const size_t row = (size_t)tile * 64 + r;
    #pragma unroll
    for (int j = 0; j < 25; j++) {
        const int c = cg * 25 + j;
        float v = (g_Part[0][p][row][c] + g_Part[1][p][row][c]
                 + g_Part[2][p][row][c] + g_Part[3][p][row][c]
                 + g_Part[4][p][row][c]) * (1.0f / WSC) + bias[c];
        v = fmaxf(v, 0.f);
        g_H1[((size_t)p * BR + row) * EMB + c] = v;
        Ds[r][c] = v;
    }
    __syncthreads();
    if (t < EMB) {
        float s = 0.f, s2 = 0.f;
        #pragma unroll 8
        for (int rr = 0; rr < 64; rr++) { float u = Ds[rr][t]; s += u; s2 += u * u; }
        g_P[0][p][tile][0][t] = s;
        g_P[0][p][tile][1][t] = s2;
    }
}

// ---------------- Layers 2-4: small GEMM with fused BN stats ---------------
// layer 0: stats over 64 tiles (from merge);  layers 1,2: over 128 tiles.
__global__ __launch_bounds__(256, 1)
void k_small(int layer, const float* __restrict__ W,
             const float* __restrict__ bias,
             const float* __restrict__ gamma, const float* __restrict__ beta,
             float* __restrict__ dout)
{
    extern __shared__ float sm[];
    float* Hs  = sm;            // 100*33
    float* Ws  = sm + 3300;     // 100*132
    float* red = sm + 16500;    // 2048 (reused: first as ss1/ss2)
    float* sc  = sm + 18548;
    float* sh  = sm + 18676;

    const int t = threadIdx.x, tile = blockIdx.x, p = blockIdx.y;
    const int r0 = tile * 32;
    const int ty = t >> 4, tx = t & 15;
    const float* Hin = (layer == 0) ? g_H1 : (layer == 1) ? g_H2 : g_H3;
    const bool rin = (layer == 2), rout = (layer == 0);
    const int nt = (layer == 0) ? 64 : 128;

    // fused BN stats (each CTA computes redundantly; deterministic order)
    float* ss1 = red;           // [128]
    float* ss2 = red + 128;     // [128]
    if (t < EMB) {
        float a = 0.f, b = 0.f, c2 = 0.f, d = 0.f;
        for (int i = 0; i < nt; i += 4) {
            a  += g_P[layer][p][i][0][t];
            b  += g_P[layer][p][i + 1][0][t];
            c2 += g_P[layer][p][i + 2][0][t];
            d  += g_P[layer][p][i + 3][0][t];
        }
        ss1[t] = (a + b) + (c2 + d);
    } else if (t >= 128 && t < 128 + EMB) {
        const int c = t - 128;
        float a = 0.f, b = 0.f, c2 = 0.f, d = 0.f;
        for (int i = 0; i < nt; i += 4) {
            a  += g_P[layer][p][i][1][c];
            b  += g_P[layer][p][i + 1][1][c];
            c2 += g_P[layer][p][i + 2][1][c];
            d  += g_P[layer][p][i + 3][1][c];
        }
        ss2[c] = (a + b) + (c2 + d);
    }
    __syncthreads();
    if (t < EMB) {
        float mu  = ss1[t] * (1.f / BR);
        float var = ss2[t] * (1.f / BR) - mu * mu;
        float s   = gamma[t] * rsqrtf(var + EPSB);
        sc[t] = s;
        sh[t] = beta[t] - mu * s;
    }
    __syncthreads();

    const float* Hp = Hin + (size_t)p * BR * EMB;
    for (int i = t; i < 32 * EMB; i += 256) {
        int row = i / EMB, k = i % EMB;
        float v = Hp[(size_t)(r0 + row) * EMB + k] * sc[k] + sh[k];
        if (rin) v = fmaxf(v, 0.f);
        Hs[k * 33 + row] = v;
    }
    for (int i = t; i < EMB * EMB; i += 256) {
        int nn = i / EMB, k = i % EMB;
        Ws[k * 132 + nn] = W[i];
    }
    for (int i = t; i < EMB * 28; i += 256) {
        int k = i / 28, nn = 100 + i % 28;
        Ws[k * 132 + nn] = 0.f;
    }
    __syncthreads();

    u64 acc[2][4];
    #pragma unroll
    for (int r = 0; r < 2; r++)
        #pragma unroll
        for (int c = 0; c < 4; c++) acc[r][c] = 0ull;

    #pragma unroll 4
    for (int k = 0; k < EMB; k++) {
        const float* ak = Hs + k * 33 + ty * 2;
        float a0 = ak[0], a1 = ak[1];
        const u64* wp = (const u64*)(Ws + k * 132 + tx * 8);
        u64 b0 = wp[0], b1 = wp[1], b2 = wp[2], b3 = wp[3];
        u64 A0 = pk2(a0, a0), A1 = pk2(a1, a1);
        acc[0][0]=fma2(A0,b0,acc[0][0]); acc[0][1]=fma2(A0,b1,acc[0][1]);
        acc[0][2]=fma2(A0,b2,acc[0][2]); acc[0][3]=fma2(A0,b3,acc[0][3]);
        acc[1][0]=fma2(A1,b0,acc[1][0]); acc[1][1]=fma2(A1,b1,acc[1][1]);
        acc[1][2]=fma2(A1,b2,acc[1][2]); acc[1][3]=fma2(A1,b3,acc[1][3]);
    }

    float* Hout = (layer == 0) ? g_H2 : g_H3;
    float vo[2][8];
    #pragma unroll
    for (int r = 0; r < 2; r++) {
        int row = r0 + ty * 2 + r;
        #pragma unroll
        for (int cp = 0; cp < 4; cp++) {
            float2 f = upk2(acc[r][cp]);
            #pragma unroll
            for (int hh = 0; hh < 2; hh++) {
                int col = tx * 8 + cp * 2 + hh;
                float v = (hh ? f.y : f.x) + (col < EMB ? bias[col] : 0.f);
                if (rout) v = fmaxf(v, 0.f);
                vo[r][cp * 2 + hh] = v;
                if (col < EMB) {
                    if (layer == 2) dout[((size_t)p * BR + row) * EMB + col] = v;
                    else            Hout[((size_t)p * BR + row) * EMB + col] = v;
                }
            }
        }
    }
    if (layer < 2) {
        __syncthreads();   // red reuse (ss1/ss2 done)
        #pragma unroll
        for (int c = 0; c < 8; c++)
            red[ty * 128 + tx * 8 + c] = vo[0][c] + vo[1][c];
        __syncthreads();
        if (t < 128) {
            float s = 0.f;
            #pragma unroll
            for (int g = 0; g < 16; g++) s += red[g * 128 + t];
            if (t < EMB) g_P[layer + 1][p][tile][0][t] = s;
        }
        __syncthreads();
        #pragma unroll
        for (int c = 0; c < 8; c++)
            red[ty * 128 + tx * 8 + c] = vo[0][c]*vo[0][c] + vo[1][c]*vo[1][c];
        __syncthreads();
        if (t < 128) {
            float s = 0.f;
            #pragma unroll
            for (int g = 0; g < 16; g++) s += red[g * 128 + t];
            if (t < EMB) g_P[layer + 1][p][tile][1][t] = s;
        }
    }
}

// ---------------- launch ----------------
extern "C" void kernel_launch(void* const* d_in, const int* in_sizes, int n_in,
                              void* d_out, int out_size)
{
    const float* x   = (const float*)d_in[0];
    const void*  mk  = d_in[1];
    const float* xr  = (const float*)d_in[2];
    const float* w1  = (const float*)d_in[3];
    const float* b1  = (const float*)d_in[4];
    const float* g1  = (const float*)d_in[5];
    const float* be1 = (const float*)d_in[6];
    const float* w2  = (const float*)d_in[7];
    const float* b2  = (const float*)d_in[8];
    const float* g2  = (const float*)d_in[9];
    const float* be2 = (const float*)d_in[10];
    const float* hw1 = (const float*)d_in[11];
    const float* hb1 = (const float*)d_in[12];
    const float* hg1 = (const float*)d_in[13];
    const float* hbe1= (const float*)d_in[14];
    const float* hw2 = (const float*)d_in[15];
    const float* hb2 = (const float*)d_in[16];
    float* out = (float*)d_out;

    cudaFuncSetAttribute(k_big,   cudaFuncAttributeMaxDynamicSharedMemorySize, NSTG * STG);
    cudaFuncSetAttribute(k_small, cudaFuncAttributeMaxDynamicSharedMemorySize, 76816);

    const int H = WROWS * MF / 2 / 2;   // 520000 pairs per half
    k_detect<<<1, 256>>>((const unsigned char*)mk);                   // 1
    k_wcvt<<<(H + 255) / 256, 256>>>(w1, 0);                          // 2
    k_wcvt<<<(H + 255) / 256, 256>>>(w1, H);                          // 3
    k_big<<<640, 256, NSTG * STG>>>(x, mk, xr);                       // 4 <- profiled
    k_merge<<<dim3(64, 2), 256>>>(b1);                                // 5
    k_small<<<dim3(128, 2), 256, 76816>>>(0, w2, b2, g1, be1, nullptr);
    k_small<<<dim3(128, 2), 256, 76816>>>(1, hw1, hb1, g2, be2, nullptr);
    k_small<<<dim3(128, 2), 256, 76816>>>(2, hw2, hb2, hg1, hbe1, out);
}

// round 12
// speedup vs baseline: 2.0193x; 1.2243x over previous
#include <cuda_runtime.h>
#include <cuda_fp16.h>
#include <cstdint>
#include <cstddef>

#define BR    4096
#define MF    20000
#define EMB   100
#define WROWS 104
#define KC    32
#define KSPL  4
#define EPSB  1e-5f
#define STG   22528         // A(p0) 4K | A(p1) 4K | Wh 7K | Wl 7K
#define NSTG  3
#define WSC   64.0f

typedef unsigned long long u64;
typedef unsigned int u32;

// ---------------- device scratch ----------------
__device__ int   g_mode;                       // 0=int32, 1=byte bool, 2=float32
__device__ unsigned short g_Wh[WROWS * MF];
__device__ unsigned short g_Wl[WROWS * MF];
__device__ float g_Part[KSPL][2][BR][104];
__device__ float g_H1[2 * BR * EMB];
__device__ float g_H2[2 * BR * EMB];
__device__ float g_H3[2 * BR * EMB];
__device__ float g_P[3][2][128][2][EMB];

// ---------------- helpers ----------------
__device__ __forceinline__ u32 smem_u32(const void* p) {
    u32 a; asm("{ .reg .u64 t; cvta.to.shared.u64 t, %1; cvt.u32.u64 %0, t; }" : "=r"(a) : "l"(p));
    return a;
}
__device__ __forceinline__ void ldsm4(u32& r0, u32& r1, u32& r2, u32& r3, u32 addr) {
    asm volatile("ldmatrix.sync.aligned.m8n8.x4.shared.b16 {%0,%1,%2,%3}, [%4];"
        : "=r"(r0), "=r"(r1), "=r"(r2), "=r"(r3) : "r"(addr));
}
__device__ __forceinline__ void mma16816(float* d, const u32* a, const u32* b) {
    asm volatile("mma.sync.aligned.m16n8k16.row.col.f32.f16.f16.f32 "
        "{%0,%1,%2,%3}, {%4,%5,%6,%7}, {%8,%9}, {%0,%1,%2,%3};"
        : "+f"(d[0]), "+f"(d[1]), "+f"(d[2]), "+f"(d[3])
        : "r"(a[0]), "r"(a[1]), "r"(a[2]), "r"(a[3]), "r"(b[0]), "r"(b[1]));
}
__device__ __forceinline__ void cp16(u32 dst, const void* src) {
    asm volatile("cp.async.cg.shared.global [%0], [%1], 16;"
        :: "r"(dst), "l"(src) : "memory");
}
#define CP_COMMIT() asm volatile("cp.async.commit_group;" ::: "memory")
#define CP_WAIT1()  asm volatile("cp.async.wait_group 1;" ::: "memory")
#define CP_WAIT0()  asm volatile("cp.async.wait_group 0;" ::: "memory")

__device__ __forceinline__ u32 sw64(u32 row, u32 colb) {
    return row * 64 + (colb ^ (((row >> 1) & 3) << 4));
}
__device__ __forceinline__ u32 pk_f16(float lo, float hi) {
    u32 r; asm("cvt.rn.f16x2.f32 %0, %1, %2;" : "=r"(r) : "f"(hi), "f"(lo));
    return r;
}
__device__ __forceinline__ u64 pk2(float lo, float hi) {
    u64 d; asm("mov.b64 %0, {%1, %2};" : "=l"(d) : "f"(lo), "f"(hi)); return d;
}
__device__ __forceinline__ u64 fma2(u64 a, u64 b, u64 c) {
    u64 d; asm("fma.rn.f32x2 %0, %1, %2, %3;" : "=l"(d) : "l"(a), "l"(b), "l"(c)); return d;
}
__device__ __forceinline__ float2 upk2(u64 v) {
    float2 r; asm("mov.b64 {%0, %1}, %2;" : "=f"(r.x), "=f"(r.y) : "l"(v)); return r;
}

// ---------------- mask dtype classifier ----------------
__global__ void k_detect(const unsigned char* __restrict__ m) {
    __shared__ int s_nz, s_gt;
    if (threadIdx.x == 0) { s_nz = 0; s_gt = 0; }
    __syncthreads();
    int nz = 0, gt = 0;
    for (int i = threadIdx.x; i < 65536; i += blockDim.x) {
        unsigned char v = m[i];
        nz += (v != 0); gt += (v > 1);
    }
    atomicAdd(&s_nz, nz); atomicAdd(&s_gt, gt);
    __syncthreads();
    if (threadIdx.x == 0)
        g_mode = (s_gt > 64) ? 2 : (s_nz > 24576) ? 1 : 0;
}

// ---------------- W split precompute ----------------
__global__ void k_wcvt(const float* __restrict__ w, int base) {
    int i = base + blockIdx.x * blockDim.x + threadIdx.x;
    if (i >= WROWS * MF / 2) return;
    int row = i / (MF / 2), within = i % (MF / 2);
    if (row < EMB) {
        float2 v = *(const float2*)(w + (size_t)row * MF + 2 * within);
        float sx = WSC * v.x, sy = WSC * v.y;
        float hx = __half2float(__float2half_rn(sx));
        float hy = __half2float(__float2half_rn(sy));
        ((u32*)g_Wh)[i] = pk_f16(hx, hy);
        ((u32*)g_Wl)[i] = pk_f16(sx - hx, sy - hy);
    } else {
        ((u32*)g_Wh)[i] = 0u;
        ((u32*)g_Wl)[i] = 0u;
    }
}

// ---------------- Layer 1: 2-term fp16 mma.sync, M=64, single wave ---------
// grid = 256: tile = bid>>2 (64 rows), ks = bid&3 (157/156/156/156 chunks).
// Stage (22528B): A(p0)@0 4K | A(p1)@4096 4K | Wh@8192 7K | Wl@15360 7K.
// Warps: pa = w>>2, nc = w&3. Each thread stages (row,seg) for BOTH passes.
__global__ __launch_bounds__(256, 2)
void k_big(const float* __restrict__ x, const void* __restrict__ mk,
           const float* __restrict__ xr)
{
    extern __shared__ char smem[];
    const u32 sb = smem_u32(smem);
    const int t = threadIdx.x;
    const int w = t >> 5, lane = t & 31;
    const int tile = blockIdx.x >> 2, ks = blockIdx.x & 3;
    const int r0g = tile * 64;
    const int ci0 = ks ? (157 + 156 * (ks - 1)) : 0;
    const int n   = ks ? 156 : 157;
    const size_t k0g = (size_t)ci0 * KC;
    const int pa = w >> 2, nc = w & 3;
    const int mode = g_mode;

    // A staging: row = t>>2 (0..63), seg = t&3; both passes per thread
    const int arow = t >> 2, seg = t & 3;
    const size_t abase = (size_t)(r0g + arow) * MF + k0g + (size_t)seg * 8;
    const u32 aoff = sw64(arow, seg * 16);

    // W cp.async map
    const int gi1 = t + 256;
    const bool w1v = (gi1 < 416);
    const int wr0 = t >> 2, wsg0 = t & 3;
    const int wr1 = gi1 >> 2, wsg1 = gi1 & 3;
    const u32 woff0 = sw64(wr0, wsg0 * 16);
    const u32 woff1 = sw64(wr1, wsg1 * 16);
    const size_t wsrc0 = (size_t)wr0 * MF + k0g + (size_t)wsg0 * 8;
    const size_t wsrc1 = (size_t)wr1 * MF + k0g + (size_t)wsg1 * 8;

    uint4 HA0, HA1;
    float acc[4][4][4];
    #pragma unroll
    for (int mf = 0; mf < 4; mf++)
        #pragma unroll
        for (int nf = 0; nf < 4; nf++)
            #pragma unroll
            for (int e = 0; e < 4; e++) acc[mf][nf][e] = 0.f;

    // zero W pad rows 104..111 in all 3 stages
    if (t < 192) {
        const int stg_i = t / 64, rem = t % 64;
        const int mat = rem >> 5, rr = 104 + ((rem & 31) >> 2), s = rem & 3;
        *(uint4*)(smem + stg_i * STG + 8192 + mat * 7168 + sw64(rr, s * 16)) =
            make_uint4(0, 0, 0, 0);
    }

    auto CPW = [&](int j) {
        const u32 base = sb + (j % 3) * STG;
        const size_t ko = (size_t)j * KC;
        cp16(base +  8192 + woff0, g_Wh + wsrc0 + ko);
        cp16(base + 15360 + woff0, g_Wl + wsrc0 + ko);
        if (w1v) {
            cp16(base +  8192 + woff1, g_Wh + wsrc1 + ko);
            cp16(base + 15360 + woff1, g_Wl + wsrc1 + ko);
        }
    };

    auto STAGE = [&](int j) {
        const size_t g = abase + (size_t)j * KC;
        float v[8], vc[8];
        float4 x0 = *(const float4*)(x + g);
        float4 x1 = *(const float4*)(x + g + 4);
        v[0]=x0.x; v[1]=x0.y; v[2]=x0.z; v[3]=x0.w;
        v[4]=x1.x; v[5]=x1.y; v[6]=x1.z; v[7]=x1.w;
        float4 q0 = *(const float4*)(xr + g);
        float4 q1 = *(const float4*)(xr + g + 4);
        float q[8] = {q0.x,q0.y,q0.z,q0.w,q1.x,q1.y,q1.z,q1.w};
        if (mode == 1) {
            uint2 mm = *(const uint2*)((const unsigned char*)mk + g);
            u32 lo = mm.x, hi = mm.y;
            #pragma unroll
            for (int m = 0; m < 4; m++) {
                vc[m]   = ((lo >> (m*8)) & 0xff) ? q[m]   : v[m];
                vc[m+4] = ((hi >> (m*8)) & 0xff) ? q[m+4] : v[m+4];
            }
        } else if (mode == 0) {
            int4 m0 = *(const int4*)((const int*)mk + g);
            int4 m1 = *(const int4*)((const int*)mk + g + 4);
            int mi[8] = {m0.x,m0.y,m0.z,m0.w,m1.x,m1.y,m1.z,m1.w};
            #pragma unroll
            for (int m = 0; m < 8; m++) vc[m] = mi[m] ? q[m] : v[m];
        } else {
            float4 m0 = *(const float4*)((const float*)mk + g);
            float4 m1 = *(const float4*)((const float*)mk + g + 4);
            float mf_[8] = {m0.x,m0.y,m0.z,m0.w,m1.x,m1.y,m1.z,m1.w};
            #pragma unroll
            for (int m = 0; m < 8; m++) vc[m] = (mf_[m] != 0.f) ? q[m] : v[m];
        }
        HA0.x = pk_f16(v[0],v[1]);  HA0.y = pk_f16(v[2],v[3]);
        HA0.z = pk_f16(v[4],v[5]);  HA0.w = pk_f16(v[6],v[7]);
        HA1.x = pk_f16(vc[0],vc[1]); HA1.y = pk_f16(vc[2],vc[3]);
        HA1.z = pk_f16(vc[4],vc[5]); HA1.w = pk_f16(vc[6],vc[7]);
    };

    auto STORE_A = [&](int j) {
        char* bs = smem + (j % 3) * STG;
        *(uint4*)(bs +        aoff) = HA0;
        *(uint4*)(bs + 4096 + aoff) = HA1;
    };

    // COMP lane addressing
    const u32 rA0 = lane & 15;
    const u32 c16A = ((lane >> 4) & 1) * 16;
    const u32 xrA0 = ((rA0 >> 1) & 3) << 4;          // mf-invariant
    const u32 nrow = nc * 32 + ((lane >> 4) & 1) * 8 + (lane & 7);
    const u32 c16B = ((lane >> 3) & 1) * 16;
    const u32 baseB0 = nrow * 64,        xrB0 = ((nrow >> 1) & 3) << 4;
    const u32 baseB1 = (nrow + 16) * 64, xrB1 = (((nrow + 16) >> 1) & 3) << 4;

    auto COMP = [&](int j) {
        const u32 bs = sb + (j % 3) * STG;
        const u32 Ab = bs + pa * 4096;
        const u32 Wh = bs + 8192, Wl = bs + 15360;
        #pragma unroll
        for (int kss = 0; kss < 2; kss++) {
            const u32 kb = kss * 32;
            const u32 ka = (kb + c16A) ^ xrA0;
            u32 aF[4][4];
            #pragma unroll
            for (int mf = 0; mf < 4; mf++)
                ldsm4(aF[mf][0], aF[mf][1], aF[mf][2], aF[mf][3],
                      Ab + rA0 * 64 + mf * 1024 + ka);
            if (nc < 3) {
                u32 bH[4][2], bL[4][2];
                ldsm4(bH[0][0], bH[0][1], bH[1][0], bH[1][1], Wh + baseB0 + ((kb + c16B) ^ xrB0));
                ldsm4(bH[2][0], bH[2][1], bH[3][0], bH[3][1], Wh + baseB1 + ((kb + c16B) ^ xrB1));
                ldsm4(bL[0][0], bL[0][1], bL[1][0], bL[1][1], Wl + baseB0 + ((kb + c16B) ^ xrB0));
                ldsm4(bL[2][0], bL[2][1], bL[3][0], bL[3][1], Wl + baseB1 + ((kb + c16B) ^ xrB1));
                #pragma unroll
                for (int mf = 0; mf < 4; mf++)
                    #pragma unroll
                    for (int nf = 0; nf < 4; nf++) {
                        mma16816(acc[mf][nf], aF[mf], bH[nf]);
                        mma16816(acc[mf][nf], aF[mf], bL[nf]);
                    }
            } else {
                u32 bH[2][2], bL[2][2];
                ldsm4(bH[0][0], bH[0][1], bH[1][0], bH[1][1], Wh + baseB0 + ((kb + c16B) ^ xrB0));
                ldsm4(bL[0][0], bL[0][1], bL[1][0], bL[1][1], Wl + baseB0 + ((kb + c16B) ^ xrB0));
                #pragma unroll
                for (int mf = 0; mf < 4; mf++)
                    #pragma unroll
                    for (int nf = 0; nf < 2; nf++) {
                        mma16816(acc[mf][nf], aF[mf], bH[nf]);
                        mma16816(acc[mf][nf], aF[mf], bL[nf]);
                    }
            }
        }
    };

    // prologue
    CPW(0); CP_COMMIT();
    CPW(1); CP_COMMIT();
    STAGE(0);
    CP_WAIT1();
    STORE_A(0);
    __syncthreads();
    STAGE(1);

    for (int i = 0; i < n; i++) {
        if (i + 1 < n) STORE_A(i + 1);
        COMP(i);
        if (i + 2 < n) { CPW(i + 2); CP_COMMIT(); CP_WAIT1(); }
        else if (i + 1 < n) CP_WAIT0();
        __syncthreads();
        if (i + 2 < n) STAGE(i + 2);
    }

    // epilogue: raw partials (scaled by 64) -> g_Part[ks][pa]
    float* Pp = &g_Part[ks][pa][0][0];
    const int gq = lane >> 2, tt = lane & 3;
    #pragma unroll
    for (int mf = 0; mf < 4; mf++)
        #pragma unroll
        for (int nf = 0; nf < 4; nf++) {
            const int col = nc * 32 + nf * 8 + 2 * tt;
            if (col < EMB) {
                const int ra = r0g + mf * 16 + gq;
                *(float2*)&Pp[(size_t)ra * 104 + col] =
                    make_float2(acc[mf][nf][0], acc[mf][nf][1]);
                *(float2*)&Pp[(size_t)(ra + 8) * 104 + col] =
                    make_float2(acc[mf][nf][2], acc[mf][nf][3]);
            }
        }
}

// ---------------- merge K-splits: unscale + bias + relu -> H1 + partials ---
__global__ void k_merge(const float* __restrict__ bias) {
    __shared__ float Ds[64][104];
    const int t = threadIdx.x, tile = blockIdx.x, p = blockIdx.y;
    const int r = t >> 2, cg = t & 3;
    const size_t row = (size_t)tile * 64 + r;
    #pragma unroll
    for (int j = 0; j < 25; j++) {
        const int c = cg * 25 + j;
        float v = (g_Part[0][p][row][c] + g_Part[1][p][row][c]
                 + g_Part[2][p][row][c] + g_Part[3][p][row][c]) * (1.0f / WSC)
                 + bias[c];
        v = fmaxf(v, 0.f);
        g_H1[((size_t)p * BR + row) * EMB + c] = v;
        Ds[r][c] = v;
    }
    __syncthreads();
    if (t < EMB) {
        float s = 0.f, s2 = 0.f;
        #pragma unroll 8
        for (int rr = 0; rr < 64; rr++) { float u = Ds[rr][t]; s += u; s2 += u * u; }
        g_P[0][p][tile][0][t] = s;
        g_P[0][p][tile][1][t] = s2;
    }
}

// ---------------- Layers 2-4: small GEMM with fused BN stats ---------------
__global__ __launch_bounds__(256, 1)
void k_small(int layer, const float* __restrict__ W,
             const float* __restrict__ bias,
             const float* __restrict__ gamma, const float* __restrict__ beta,
             float* __restrict__ dout)
{
    extern __shared__ float sm[];
    float* Hs  = sm;            // 100*33
    float* Ws  = sm + 3300;     // 100*132
    float* red = sm + 16500;    // 2048
    float* sc  = sm + 18548;
    float* sh  = sm + 18676;

    const int t = threadIdx.x, tile = blockIdx.x, p = blockIdx.y;
    const int r0 = tile * 32;
    const int ty = t >> 4, tx = t & 15;
    const float* Hin = (layer == 0) ? g_H1 : (layer == 1) ? g_H2 : g_H3;
    const bool rin = (layer == 2), rout = (layer == 0);
    const int nt = (layer == 0) ? 64 : 128;

    float* ss1 = red;
    float* ss2 = red + 128;
    if (t < EMB) {
        float a = 0.f, b = 0.f, c2 = 0.f, d = 0.f;
        for (int i = 0; i < nt; i += 4) {
            a  += g_P[layer][p][i][0][t];
            b  += g_P[layer][p][i + 1][0][t];
            c2 += g_P[layer][p][i + 2][0][t];
            d  += g_P[layer][p][i + 3][0][t];
        }
        ss1[t] = (a + b) + (c2 + d);
    } else if (t >= 128 && t < 128 + EMB) {
        const int c = t - 128;
        float a = 0.f, b = 0.f, c2 = 0.f, d = 0.f;
        for (int i = 0; i < nt; i += 4) {
            a  += g_P[layer][p][i][1][c];
            b  += g_P[layer][p][i + 1][1][c];
            c2 += g_P[layer][p][i + 2][1][c];
            d  += g_P[layer][p][i + 3][1][c];
        }
        ss2[c] = (a + b) + (c2 + d);
    }
    __syncthreads();
    if (t < EMB) {
        float mu  = ss1[t] * (1.f / BR);
        float var = ss2[t] * (1.f / BR) - mu * mu;
        float s   = gamma[t] * rsqrtf(var + EPSB);
        sc[t] = s;
        sh[t] = beta[t] - mu * s;
    }
    __syncthreads();

    const float* Hp = Hin + (size_t)p * BR * EMB;
    for (int i = t; i < 32 * EMB; i += 256) {
        int row = i / EMB, k = i % EMB;
        float v = Hp[(size_t)(r0 + row) * EMB + k] * sc[k] + sh[k];
        if (rin) v = fmaxf(v, 0.f);
        Hs[k * 33 + row] = v;
    }
    for (int i = t; i < EMB * EMB; i += 256) {
        int nn = i / EMB, k = i % EMB;
        Ws[k * 132 + nn] = W[i];
    }
    for (int i = t; i < EMB * 28; i += 256) {
        int k = i / 28, nn = 100 + i % 28;
        Ws[k * 132 + nn] = 0.f;
    }
    __syncthreads();

    u64 acc[2][4];
    #pragma unroll
    for (int r = 0; r < 2; r++)
        #pragma unroll
        for (int c = 0; c < 4; c++) acc[r][c] = 0ull;

    #pragma unroll 4
    for (int k = 0; k < EMB; k++) {
        const float* ak = Hs + k * 33 + ty * 2;
        float a0 = ak[0], a1 = ak[1];
        const u64* wp = (const u64*)(Ws + k * 132 + tx * 8);
        u64 b0 = wp[0], b1 = wp[1], b2 = wp[2], b3 = wp[3];
        u64 A0 = pk2(a0, a0), A1 = pk2(a1, a1);
        acc[0][0]=fma2(A0,b0,acc[0][0]); acc[0][1]=fma2(A0,b1,acc[0][1]);
        acc[0][2]=fma2(A0,b2,acc[0][2]); acc[0][3]=fma2(A0,b3,acc[0][3]);
        acc[1][0]=fma2(A1,b0,acc[1][0]); acc[1][1]=fma2(A1,b1,acc[1][1]);
        acc[1][2]=fma2(A1,b2,acc[1][2]); acc[1][3]=fma2(A1,b3,acc[1][3]);
    }

    float* Hout = (layer == 0) ? g_H2 : g_H3;
    float vo[2][8];
    #pragma unroll
    for (int r = 0; r < 2; r++) {
        int row = r0 + ty * 2 + r;
        #pragma unroll
        for (int cp = 0; cp < 4; cp++) {
            float2 f = upk2(acc[r][cp]);
            #pragma unroll
            for (int hh = 0; hh < 2; hh++) {
                int col = tx * 8 + cp * 2 + hh;
                float v = (hh ? f.y : f.x) + (col < EMB ? bias[col] : 0.f);
                if (rout) v = fmaxf(v, 0.f);
                vo[r][cp * 2 + hh] = v;
                if (col < EMB) {
                    if (layer == 2) dout[((size_t)p * BR + row) * EMB + col] = v;
                    else            Hout[((size_t)p * BR + row) * EMB + col] = v;
                }
            }
        }
    }
    if (layer < 2) {
        __syncthreads();
        #pragma unroll
        for (int c = 0; c < 8; c++)
            red[ty * 128 + tx * 8 + c] = vo[0][c] + vo[1][c];
        __syncthreads();
        if (t < 128) {
            float s = 0.f;
            #pragma unroll
            for (int g = 0; g < 16; g++) s += red[g * 128 + t];
            if (t < EMB) g_P[layer + 1][p][tile][0][t] = s;
        }
        __syncthreads();
        #pragma unroll
        for (int c = 0; c < 8; c++)
            red[ty * 128 + tx * 8 + c] = vo[0][c]*vo[0][c] + vo[1][c]*vo[1][c];
        __syncthreads();
        if (t < 128) {
            float s = 0.f;
            #pragma unroll
            for (int g = 0; g < 16; g++) s += red[g * 128 + t];
            if (t < EMB) g_P[layer + 1][p][tile][1][t] = s;
        }
    }
}

// ---------------- launch ----------------
extern "C" void kernel_launch(void* const* d_in, const int* in_sizes, int n_in,
                              void* d_out, int out_size)
{
    const float* x   = (const float*)d_in[0];
    const void*  mk  = d_in[1];
    const float* xr  = (const float*)d_in[2];
    const float* w1  = (const float*)d_in[3];
    const float* b1  = (const float*)d_in[4];
    const float* g1  = (const float*)d_in[5];
    const float* be1 = (const float*)d_in[6];
    const float* w2  = (const float*)d_in[7];
    const float* b2  = (const float*)d_in[8];
    const float* g2  = (const float*)d_in[9];
    const float* be2 = (const float*)d_in[10];
    const float* hw1 = (const float*)d_in[11];
    const float* hb1 = (const float*)d_in[12];
    const float* hg1 = (const float*)d_in[13];
    const float* hbe1= (const float*)d_in[14];
    const float* hw2 = (const float*)d_in[15];
    const float* hb2 = (const float*)d_in[16];
    float* out = (float*)d_out;

    cudaFuncSetAttribute(k_big,   cudaFuncAttributeMaxDynamicSharedMemorySize, NSTG * STG);
    cudaFuncSetAttribute(k_small, cudaFuncAttributeMaxDynamicSharedMemorySize, 76816);

    const int H = WROWS * MF / 2 / 2;
    k_detect<<<1, 256>>>((const unsigned char*)mk);                   // 1
    k_wcvt<<<(H + 255) / 256, 256>>>(w1, 0);                          // 2
    k_wcvt<<<(H + 255) / 256, 256>>>(w1, H);                          // 3
    k_big<<<256, 256, NSTG * STG>>>(x, mk, xr);                       // 4 <- profiled
    k_merge<<<dim3(64, 2), 256>>>(b1);                                // 5
    k_small<<<dim3(128, 2), 256, 76816>>>(0, w2, b2, g1, be1, nullptr);
    k_small<<<dim3(128, 2), 256, 76816>>>(1, hw1, hb1, g2, be2, nullptr);
    k_small<<<dim3(128, 2), 256, 76816>>>(2, hw2, hb2, hg1, hbe1, out);
}

// round 13
// speedup vs baseline: 2.0290x; 1.0048x over previous
#include <cuda_runtime.h>
#include <cuda_fp16.h>
#include <cstdint>
#include <cstddef>

#define BR    4096
#define MF    20000
#define EMB   100
#define WROWS 104
#define KC    32
#define KSPL  4
#define EPSB  1e-5f
#define STG   22528         // A(p0) 4K | A(p1) 4K | Wh 7K | Wl 7K
#define NSTG  4
#define WSC   64.0f

typedef unsigned long long u64;
typedef unsigned int u32;

// ---------------- device scratch ----------------
__device__ int   g_mode;                       // 0=int32, 1=byte bool, 2=float32
__device__ unsigned short g_Wh[WROWS * MF];
__device__ unsigned short g_Wl[WROWS * MF];
__device__ float g_Part[KSPL][2][BR][104];
__device__ float g_H1[2 * BR * EMB];
__device__ float g_H2[2 * BR * EMB];
__device__ float g_H3[2 * BR * EMB];
__device__ float g_P[3][2][128][2][EMB];

// ---------------- helpers ----------------
__device__ __forceinline__ u32 smem_u32(const void* p) {
    u32 a; asm("{ .reg .u64 t; cvta.to.shared.u64 t, %1; cvt.u32.u64 %0, t; }" : "=r"(a) : "l"(p));
    return a;
}
__device__ __forceinline__ void ldsm4(u32& r0, u32& r1, u32& r2, u32& r3, u32 addr) {
    asm volatile("ldmatrix.sync.aligned.m8n8.x4.shared.b16 {%0,%1,%2,%3}, [%4];"
        : "=r"(r0), "=r"(r1), "=r"(r2), "=r"(r3) : "r"(addr));
}
__device__ __forceinline__ void mma16816(float* d, const u32* a, const u32* b) {
    asm volatile("mma.sync.aligned.m16n8k16.row.col.f32.f16.f16.f32 "
        "{%0,%1,%2,%3}, {%4,%5,%6,%7}, {%8,%9}, {%0,%1,%2,%3};"
        : "+f"(d[0]), "+f"(d[1]), "+f"(d[2]), "+f"(d[3])
        : "r"(a[0]), "r"(a[1]), "r"(a[2]), "r"(a[3]), "r"(b[0]), "r"(b[1]));
}
__device__ __forceinline__ void cp16(u32 dst, const void* src) {
    asm volatile("cp.async.cg.shared.global [%0], [%1], 16;"
        :: "r"(dst), "l"(src) : "memory");
}
#define CP_COMMIT() asm volatile("cp.async.commit_group;" ::: "memory")
#define CP_WAIT1()  asm volatile("cp.async.wait_group 1;" ::: "memory")
#define CP_WAIT0()  asm volatile("cp.async.wait_group 0;" ::: "memory")

__device__ __forceinline__ u32 sw64(u32 row, u32 colb) {
    return row * 64 + (colb ^ (((row >> 1) & 3) << 4));
}
__device__ __forceinline__ u32 pk_f16(float lo, float hi) {
    u32 r; asm("cvt.rn.f16x2.f32 %0, %1, %2;" : "=r"(r) : "f"(hi), "f"(lo));
    return r;
}
__device__ __forceinline__ u64 pk2(float lo, float hi) {
    u64 d; asm("mov.b64 %0, {%1, %2};" : "=l"(d) : "f"(lo), "f"(hi)); return d;
}
__device__ __forceinline__ u64 fma2(u64 a, u64 b, u64 c) {
    u64 d; asm("fma.rn.f32x2 %0, %1, %2, %3;" : "=l"(d) : "l"(a), "l"(b), "l"(c)); return d;
}
__device__ __forceinline__ float2 upk2(u64 v) {
    float2 r; asm("mov.b64 {%0, %1}, %2;" : "=f"(r.x), "=f"(r.y) : "l"(v)); return r;
}

// ---------------- mask dtype classifier ----------------
__global__ void k_detect(const unsigned char* __restrict__ m) {
    __shared__ int s_nz, s_gt;
    if (threadIdx.x == 0) { s_nz = 0; s_gt = 0; }
    __syncthreads();
    int nz = 0, gt = 0;
    for (int i = threadIdx.x; i < 65536; i += blockDim.x) {
        unsigned char v = m[i];
        nz += (v != 0); gt += (v > 1);
    }
    atomicAdd(&s_nz, nz); atomicAdd(&s_gt, gt);
    __syncthreads();
    if (threadIdx.x == 0)
        g_mode = (s_gt > 64) ? 2 : (s_nz > 24576) ? 1 : 0;
}

// ---------------- W split precompute ----------------
__global__ void k_wcvt(const float* __restrict__ w, int base) {
    int i = base + blockIdx.x * blockDim.x + threadIdx.x;
    if (i >= WROWS * MF / 2) return;
    int row = i / (MF / 2), within = i % (MF / 2);
    if (row < EMB) {
        float2 v = *(const float2*)(w + (size_t)row * MF + 2 * within);
        float sx = WSC * v.x, sy = WSC * v.y;
        float hx = __half2float(__float2half_rn(sx));
        float hy = __half2float(__float2half_rn(sy));
        ((u32*)g_Wh)[i] = pk_f16(hx, hy);
        ((u32*)g_Wl)[i] = pk_f16(sx - hx, sy - hy);
    } else {
        ((u32*)g_Wh)[i] = 0u;
        ((u32*)g_Wl)[i] = 0u;
    }
}

// ---------------- Layer 1: 2-term fp16 mma.sync, 4-stage, 2 chunks/barrier -
// grid = 256: tile = bid>>2 (64 rows), ks = bid&3 (157/156/156/156 chunks).
// Stage (22528B): A(p0)@0 4K | A(p1)@4096 4K | Wh@8192 7K | Wl@15360 7K.
__global__ __launch_bounds__(256, 2)
void k_big(const float* __restrict__ x, const void* __restrict__ mk,
           const float* __restrict__ xr)
{
    extern __shared__ char smem[];
    const u32 sb = smem_u32(smem);
    const int t = threadIdx.x;
    const int w = t >> 5, lane = t & 31;
    const int tile = blockIdx.x >> 2, ks = blockIdx.x & 3;
    const int r0g = tile * 64;
    const int ci0 = ks ? (157 + 156 * (ks - 1)) : 0;
    const int n   = ks ? 156 : 157;
    const size_t k0g = (size_t)ci0 * KC;
    const int pa = w >> 2, nc = w & 3;
    const int mode = g_mode;

    // A staging: row = t>>2 (0..63), seg = t&3; both passes per thread
    const int arow = t >> 2, seg = t & 3;
    const size_t abase = (size_t)(r0g + arow) * MF + k0g + (size_t)seg * 8;
    const u32 aoff = sw64(arow, seg * 16);

    // W cp.async map
    const int gi1 = t + 256;
    const bool w1v = (gi1 < 416);
    const int wr0 = t >> 2, wsg0 = t & 3;
    const int wr1 = gi1 >> 2, wsg1 = gi1 & 3;
    const u32 woff0 = sw64(wr0, wsg0 * 16);
    const u32 woff1 = sw64(wr1, wsg1 * 16);
    const size_t wsrc0 = (size_t)wr0 * MF + k0g + (size_t)wsg0 * 8;
    const size_t wsrc1 = (size_t)wr1 * MF + k0g + (size_t)wsg1 * 8;

    float acc[4][4][4];
    #pragma unroll
    for (int mf = 0; mf < 4; mf++)
        #pragma unroll
        for (int nf = 0; nf < 4; nf++)
            #pragma unroll
            for (int e = 0; e < 4; e++) acc[mf][nf][e] = 0.f;

    // zero W pad rows 104..111 in all 4 stages (one 16B unit per thread)
    {
        const int stg_i = t >> 6, rem = t & 63;
        const int mat = rem >> 5, rr = 104 + ((rem & 31) >> 2), s = rem & 3;
        *(uint4*)(smem + stg_i * STG + 8192 + mat * 7168 + sw64(rr, s * 16)) =
            make_uint4(0, 0, 0, 0);
    }

    auto CPW = [&](int j) {
        const u32 base = sb + (j & 3) * STG;
        const size_t ko = (size_t)j * KC;
        cp16(base +  8192 + woff0, g_Wh + wsrc0 + ko);
        cp16(base + 15360 + woff0, g_Wl + wsrc0 + ko);
        if (w1v) {
            cp16(base +  8192 + woff1, g_Wh + wsrc1 + ko);
            cp16(base + 15360 + woff1, g_Wl + wsrc1 + ko);
        }
    };

    // STAGE j: load + blend + pack + store straight into stage j&3
    auto STAGE = [&](int j) {
        const size_t g = abase + (size_t)j * KC;
        float v[8], vc[8];
        float4 x0 = *(const float4*)(x + g);
        float4 x1 = *(const float4*)(x + g + 4);
        v[0]=x0.x; v[1]=x0.y; v[2]=x0.z; v[3]=x0.w;
        v[4]=x1.x; v[5]=x1.y; v[6]=x1.z; v[7]=x1.w;
        float4 q0 = *(const float4*)(xr + g);
        float4 q1 = *(const float4*)(xr + g + 4);
        float q[8] = {q0.x,q0.y,q0.z,q0.w,q1.x,q1.y,q1.z,q1.w};
        if (mode == 1) {
            uint2 mm = *(const uint2*)((const unsigned char*)mk + g);
            u32 lo = mm.x, hi = mm.y;
            #pragma unroll
            for (int m = 0; m < 4; m++) {
                vc[m]   = ((lo >> (m*8)) & 0xff) ? q[m]   : v[m];
                vc[m+4] = ((hi >> (m*8)) & 0xff) ? q[m+4] : v[m+4];
            }
        } else if (mode == 0) {
            int4 m0 = *(const int4*)((const int*)mk + g);
            int4 m1 = *(const int4*)((const int*)mk + g + 4);
            int mi[8] = {m0.x,m0.y,m0.z,m0.w,m1.x,m1.y,m1.z,m1.w};
            #pragma unroll
            for (int m = 0; m < 8; m++) vc[m] = mi[m] ? q[m] : v[m];
        } else {
            float4 m0 = *(const float4*)((const float*)mk + g);
            float4 m1 = *(const float4*)((const float*)mk + g + 4);
            float mf_[8] = {m0.x,m0.y,m0.z,m0.w,m1.x,m1.y,m1.z,m1.w};
            #pragma unroll
            for (int m = 0; m < 8; m++) vc[m] = (mf_[m] != 0.f) ? q[m] : v[m];
        }
        uint4 HA0, HA1;
        HA0.x = pk_f16(v[0],v[1]);  HA0.y = pk_f16(v[2],v[3]);
        HA0.z = pk_f16(v[4],v[5]);  HA0.w = pk_f16(v[6],v[7]);
        HA1.x = pk_f16(vc[0],vc[1]); HA1.y = pk_f16(vc[2],vc[3]);
        HA1.z = pk_f16(vc[4],vc[5]); HA1.w = pk_f16(vc[6],vc[7]);
        char* bs = smem + (j & 3) * STG;
        *(uint4*)(bs +        aoff) = HA0;
        *(uint4*)(bs + 4096 + aoff) = HA1;
    };

    // COMP lane addressing
    const u32 rA0 = lane & 15;
    const u32 c16A = ((lane >> 4) & 1) * 16;
    const u32 xrA0 = ((rA0 >> 1) & 3) << 4;
    const u32 nrow = nc * 32 + ((lane >> 4) & 1) * 8 + (lane & 7);
    const u32 c16B = ((lane >> 3) & 1) * 16;
    const u32 baseB0 = nrow * 64,        xrB0 = ((nrow >> 1) & 3) << 4;
    const u32 baseB1 = (nrow + 16) * 64, xrB1 = (((nrow + 16) >> 1) & 3) << 4;

    auto COMP = [&](int j) {
        const u32 bs = sb + (j & 3) * STG;
        const u32 Ab = bs + pa * 4096;
        const u32 Wh = bs + 8192, Wl = bs + 15360;
        #pragma unroll
        for (int kss = 0; kss < 2; kss++) {
            const u32 kb = kss * 32;
            const u32 ka = (kb + c16A) ^ xrA0;
            u32 aF[4][4];
            #pragma unroll
            for (int mf = 0; mf < 4; mf++)
                ldsm4(aF[mf][0], aF[mf][1], aF[mf][2], aF[mf][3],
                      Ab + rA0 * 64 + mf * 1024 + ka);
            if (nc < 3) {
                u32 bH[4][2], bL[4][2];
                ldsm4(bH[0][0], bH[0][1], bH[1][0], bH[1][1], Wh + baseB0 + ((kb + c16B) ^ xrB0));
                ldsm4(bH[2][0], bH[2][1], bH[3][0], bH[3][1], Wh + baseB1 + ((kb + c16B) ^ xrB1));
                ldsm4(bL[0][0], bL[0][1], bL[1][0], bL[1][1], Wl + baseB0 + ((kb + c16B) ^ xrB0));
                ldsm4(bL[2][0], bL[2][1], bL[3][0], bL[3][1], Wl + baseB1 + ((kb + c16B) ^ xrB1));
                #pragma unroll
                for (int mf = 0; mf < 4; mf++)
                    #pragma unroll
                    for (int nf = 0; nf < 4; nf++) {
                        mma16816(acc[mf][nf], aF[mf], bH[nf]);
                        mma16816(acc[mf][nf], aF[mf], bL[nf]);
                    }
            } else {
                u32 bH[2][2], bL[2][2];
                ldsm4(bH[0][0], bH[0][1], bH[1][0], bH[1][1], Wh + baseB0 + ((kb + c16B) ^ xrB0));
                ldsm4(bL[0][0], bL[0][1], bL[1][0], bL[1][1], Wl + baseB0 + ((kb + c16B) ^ xrB0));
                #pragma unroll
                for (int mf = 0; mf < 4; mf++)
                    #pragma unroll
                    for (int nf = 0; nf < 2; nf++) {
                        mma16816(acc[mf][nf], aF[mf], bH[nf]);
                        mma16816(acc[mf][nf], aF[mf], bL[nf]);
                    }
            }
        }
    };

    // prologue: W0..W2 in flight (3 groups), A0..A1 staged
    CPW(0); CP_COMMIT();
    CPW(1); CP_COMMIT();
    CPW(2); CP_COMMIT();
    STAGE(0);
    STAGE(1);
    CP_WAIT1();                  // W0, W1 complete
    __syncthreads();

    // main loop: 2 chunks per barrier. Invariant at loop top: A(i),A(i+1)
    // stored & visible; W(i),W(i+1) complete & visible; group for W(i+2) pending.
    int i = 0;
    for (; i + 1 < n; i += 2) {
        COMP(i);
        if (i + 2 < n) STAGE(i + 2);     // writes stage (i+2)&3 (free)
        COMP(i + 1);
        if (i + 3 < n) STAGE(i + 3);     // writes stage (i+3)&3 (free)
        if (i + 3 < n) CPW(i + 3);
        CP_COMMIT();                     // group always committed (may be empty)
        if (i + 4 < n) CPW(i + 4);
        CP_COMMIT();
        CP_WAIT1();                      // W(i+2), W(i+3) complete
        __syncthreads();
    }
    if (i < n) COMP(i);                  // odd tail (ks==0: chunk 156)

    // epilogue: raw partials (scaled by 64) -> g_Part[ks][pa]
    float* Pp = &g_Part[ks][pa][0][0];
    const int gq = lane >> 2, tt = lane & 3;
    #pragma unroll
    for (int mf = 0; mf < 4; mf++)
        #pragma unroll
        for (int nf = 0; nf < 4; nf++) {
            const int col = nc * 32 + nf * 8 + 2 * tt;
            if (col < EMB) {
                const int ra = r0g + mf * 16 + gq;
                *(float2*)&Pp[(size_t)ra * 104 + col] =
                    make_float2(acc[mf][nf][0], acc[mf][nf][1]);
                *(float2*)&Pp[(size_t)(ra + 8) * 104 + col] =
                    make_float2(acc[mf][nf][2], acc[mf][nf][3]);
            }
        }
}

// ---------------- merge K-splits: unscale + bias + relu -> H1 + partials ---
__global__ void k_merge(const float* __restrict__ bias) {
    __shared__ float Ds[64][104];
    const int t = threadIdx.x, tile = blockIdx.x, p = blockIdx.y;
    const int r = t >> 2, cg = t & 3;
    const size_t row = (size_t)tile * 64 + r;
    #pragma unroll
    for (int j = 0; j < 25; j++) {
        const int c = cg * 25 + j;
        float v = (g_Part[0][p][row][c] + g_Part[1][p][row][c]
                 + g_Part[2][p][row][c] + g_Part[3][p][row][c]) * (1.0f / WSC)
                 + bias[c];
        v = fmaxf(v, 0.f);
        g_H1[((size_t)p * BR + row) * EMB + c] = v;
        Ds[r][c] = v;
    }
    __syncthreads();
    if (t < EMB) {
        float s = 0.f, s2 = 0.f;
        #pragma unroll 8
        for (int rr = 0; rr < 64; rr++) { float u = Ds[rr][t]; s += u; s2 += u * u; }
        g_P[0][p][tile][0][t] = s;
        g_P[0][p][tile][1][t] = s2;
    }
}

// ---------------- Layers 2-4: small GEMM with fused BN stats, occ 2 --------
__global__ __launch_bounds__(256, 2)
void k_small(int layer, const float* __restrict__ W,
             const float* __restrict__ bias,
             const float* __restrict__ gamma, const float* __restrict__ beta,
             float* __restrict__ dout)
{
    extern __shared__ float sm[];
    float* Hs  = sm;            // 100*33
    float* Ws  = sm + 3300;     // 100*132
    float* red = sm + 16500;    // 2048
    float* sc  = sm + 18548;
    float* sh  = sm + 18676;

    const int t = threadIdx.x, tile = blockIdx.x, p = blockIdx.y;
    const int r0 = tile * 32;
    const int ty = t >> 4, tx = t & 15;
    const float* Hin = (layer == 0) ? g_H1 : (layer == 1) ? g_H2 : g_H3;
    const bool rin = (layer == 2), rout = (layer == 0);
    const int nt = (layer == 0) ? 64 : 128;

    float* ss1 = red;
    float* ss2 = red + 128;
    if (t < EMB) {
        float a = 0.f, b = 0.f, c2 = 0.f, d = 0.f;
        for (int i = 0; i < nt; i += 4) {
            a  += g_P[layer][p][i][0][t];
            b  += g_P[layer][p][i + 1][0][t];
            c2 += g_P[layer][p][i + 2][0][t];
            d  += g_P[layer][p][i + 3][0][t];
        }
        ss1[t] = (a + b) + (c2 + d);
    } else if (t >= 128 && t < 128 + EMB) {
        const int c = t - 128;
        float a = 0.f, b = 0.f, c2 = 0.f, d = 0.f;
        for (int i = 0; i < nt; i += 4) {
            a  += g_P[layer][p][i][1][c];
            b  += g_P[layer][p][i + 1][1][c];
            c2 += g_P[layer][p][i + 2][1][c];
            d  += g_P[layer][p][i + 3][1][c];
        }
        ss2[c] = (a + b) + (c2 + d);
    }
    __syncthreads();
    if (t < EMB) {
        float mu  = ss1[t] * (1.f / BR);
        float var = ss2[t] * (1.f / BR) - mu * mu;
        float s   = gamma[t] * rsqrtf(var + EPSB);
        sc[t] = s;
        sh[t] = beta[t] - mu * s;
    }
    __syncthreads();

    const float* Hp = Hin + (size_t)p * BR * EMB;
    for (int i = t; i < 32 * EMB; i += 256) {
        int row = i / EMB, k = i % EMB;
        float v = Hp[(size_t)(r0 + row) * EMB + k] * sc[k] + sh[k];
        if (rin) v = fmaxf(v, 0.f);
        Hs[k * 33 + row] = v;
    }
    for (int i = t; i < EMB * EMB; i += 256) {
        int nn = i / EMB, k = i % EMB;
        Ws[k * 132 + nn] = W[i];
    }
    for (int i = t; i < EMB * 28; i += 256) {
        int k = i / 28, nn = 100 + i % 28;
        Ws[k * 132 + nn] = 0.f;
    }
    __syncthreads();

    u64 acc[2][4];
    #pragma unroll
    for (int r = 0; r < 2; r++)
        #pragma unroll
        for (int c = 0; c < 4; c++) acc[r][c] = 0ull;

    #pragma unroll 4
    for (int k = 0; k < EMB; k++) {
        const float* ak = Hs + k * 33 + ty * 2;
        float a0 = ak[0], a1 = ak[1];
        const u64* wp = (const u64*)(Ws + k * 132 + tx * 8);
        u64 b0 = wp[0], b1 = wp[1], b2 = wp[2], b3 = wp[3];
        u64 A0 = pk2(a0, a0), A1 = pk2(a1, a1);
        acc[0][0]=fma2(A0,b0,acc[0][0]); acc[0][1]=fma2(A0,b1,acc[0][1]);
        acc[0][2]=fma2(A0,b2,acc[0][2]); acc[0][3]=fma2(A0,b3,acc[0][3]);
        acc[1][0]=fma2(A1,b0,acc[1][0]); acc[1][1]=fma2(A1,b1,acc[1][1]);
        acc[1][2]=fma2(A1,b2,acc[1][2]); acc[1][3]=fma2(A1,b3,acc[1][3]);
    }

    float* Hout = (layer == 0) ? g_H2 : g_H3;
    float vo[2][8];
    #pragma unroll
    for (int r = 0; r < 2; r++) {
        int row = r0 + ty * 2 + r;
        #pragma unroll
        for (int cp = 0; cp < 4; cp++) {
            float2 f = upk2(acc[r][cp]);
            #pragma unroll
            for (int hh = 0; hh < 2; hh++) {
                int col = tx * 8 + cp * 2 + hh;
                float v = (hh ? f.y : f.x) + (col < EMB ? bias[col] : 0.f);
                if (rout) v = fmaxf(v, 0.f);
                vo[r][cp * 2 + hh] = v;
                if (col < EMB) {
                    if (layer == 2) dout[((size_t)p * BR + row) * EMB + col] = v;
                    else            Hout[((size_t)p * BR + row) * EMB + col] = v;
                }
            }
        }
    }
    if (layer < 2) {
        __syncthreads();
        #pragma unroll
        for (int c = 0; c < 8; c++)
            red[ty * 128 + tx * 8 + c] = vo[0][c] + vo[1][c];
        __syncthreads();
        if (t < 128) {
            float s = 0.f;
            #pragma unroll
            for (int g = 0; g < 16; g++) s += red[g * 128 + t];
            if (t < EMB) g_P[layer + 1][p][tile][0][t] = s;
        }
        __syncthreads();
        #pragma unroll
        for (int c = 0; c < 8; c++)
            red[ty * 128 + tx * 8 + c] = vo[0][c]*vo[0][c] + vo[1][c]*vo[1][c];
        __syncthreads();
        if (t < 128) {
            float s = 0.f;
            #pragma unroll
            for (int g = 0; g < 16; g++) s += red[g * 128 + t];
            if (t < EMB) g_P[layer + 1][p][tile][1][t] = s;
        }
    }
}

// ---------------- launch ----------------
extern "C" void kernel_launch(void* const* d_in, const int* in_sizes, int n_in,
                              void* d_out, int out_size)
{
    const float* x   = (const float*)d_in[0];
    const void*  mk  = d_in[1];
    const float* xr  = (const float*)d_in[2];
    const float* w1  = (const float*)d_in[3];
    const float* b1  = (const float*)d_in[4];
    const float* g1  = (const float*)d_in[5];
    const float* be1 = (const float*)d_in[6];
    const float* w2  = (const float*)d_in[7];
    const float* b2  = (const float*)d_in[8];
    const float* g2  = (const float*)d_in[9];
    const float* be2 = (const float*)d_in[10];
    const float* hw1 = (const float*)d_in[11];
    const float* hb1 = (const float*)d_in[12];
    const float* hg1 = (const float*)d_in[13];
    const float* hbe1= (const float*)d_in[14];
    const float* hw2 = (const float*)d_in[15];
    const float* hb2 = (const float*)d_in[16];
    float* out = (float*)d_out;

    cudaFuncSetAttribute(k_big,   cudaFuncAttributeMaxDynamicSharedMemorySize, NSTG * STG);
    cudaFuncSetAttribute(k_small, cudaFuncAttributeMaxDynamicSharedMemorySize, 76816);

    const int H = WROWS * MF / 2 / 2;
    k_detect<<<1, 256>>>((const unsigned char*)mk);                   // 1
    k_wcvt<<<(H + 255) / 256, 256>>>(w1, 0);                          // 2
    k_wcvt<<<(H + 255) / 256, 256>>>(w1, H);                          // 3
    k_big<<<256, 256, NSTG * STG>>>(x, mk, xr);                       // 4 <- profiled
    k_merge<<<dim3(64, 2), 256>>>(b1);                                // 5
    k_small<<<dim3(128, 2), 256, 76816>>>(0, w2, b2, g1, be1, nullptr);
    k_small<<<dim3(128, 2), 256, 76816>>>(1, hw1, hb1, g2, be2, nullptr);
    k_small<<<dim3(128, 2), 256, 76816>>>(2, hw2, hb2, hg1, hbe1, out);
}